// round 2
// baseline (speedup 1.0000x reference)
#include <cuda_runtime.h>
#include <math.h>

// ---------------------------------------------------------------------------
// Problem constants
// ---------------------------------------------------------------------------
#define BB 4
#define NSEQ 1024
#define DM 1024
#define NH 16
#define HD 64
#define TD 768
#define TL 77
#define TTOK (BB * NSEQ)   // 4096
#define TCTX (BB * TL)     // 308

// ---------------------------------------------------------------------------
// Scratch (static device globals; no allocation allowed)
// ---------------------------------------------------------------------------
__device__ float g_mod[BB * 6 * DM];            // adaLN chunks
__device__ float g_h[TTOK * DM];                // LN+modulate output (reused 3x)
__device__ float g_qkv[TTOK * 3 * DM];          // self-attn qkv
__device__ float g_attn[TTOK * DM];             // attention outputs (reused)
__device__ float g_x1[TTOK * DM];               // x after self-attn
__device__ float g_x2[TTOK * DM];               // x after cross-attn
__device__ float g_ctx[TCTX * DM];              // projected text context
__device__ float g_qb[TTOK * DM];               // cross-attn queries
__device__ float g_kc[TCTX * DM];               // cross-attn keys
__device__ float g_vc[TCTX * DM];               // cross-attn values
__device__ float g_hidden[TTOK * 4 * DM];       // MLP hidden

// ---------------------------------------------------------------------------
// Helpers
// ---------------------------------------------------------------------------
__device__ __forceinline__ float gelu_tanh(float x) {
    float x3 = x * x * x;
    float t  = tanhf(0.7978845608028654f * (x + 0.044715f * x3));
    return 0.5f * x * (1.0f + t);
}

// Epilogue modes
#define EPI_BIAS      0
#define EPI_BIAS_GELU 1
#define EPI_BIAS_RES  2
#define EPI_NOBIAS    3

// ---------------------------------------------------------------------------
// Generic SGEMM: C[M,N] = A[M,K] @ W[K,N] (+bias) (+gelu) (+residual)
// BM=BN=128, BK=8, 256 threads, 8x8 per thread (split 4+4 for float4 access)
// N and K must be multiples of 128 / 8 respectively (true for all calls).
// ---------------------------------------------------------------------------
template <int EPI>
__global__ void __launch_bounds__(256) sgemm_kernel(
    const float* __restrict__ A, const float* __restrict__ W,
    const float* __restrict__ bias, const float* __restrict__ res,
    float* __restrict__ C, int M, int N, int K)
{
    __shared__ float As[8][128];
    __shared__ float Ws[8][128];

    const int tid = threadIdx.x;
    const int tx = tid & 15;       // 0..15 (cols)
    const int ty = tid >> 4;       // 0..15 (rows)
    const int rowBase = blockIdx.y * 128;
    const int colBase = blockIdx.x * 128;

    float acc[8][8];
#pragma unroll
    for (int i = 0; i < 8; i++)
#pragma unroll
        for (int j = 0; j < 8; j++) acc[i][j] = 0.0f;

    // A-load mapping: one float4 per thread (128 rows x 8 k = 256 float4)
    const int ar   = tid >> 1;      // row in tile
    const int ahalf= (tid & 1) * 4; // which half of 8-k
    // W-load mapping: one float4 per thread (8 k x 128 cols)
    const int wk = tid >> 5;        // 0..7
    const int wc = (tid & 31) * 4;  // 0..124

    for (int k0 = 0; k0 < K; k0 += 8) {
        const int gr = rowBase + ar;
        float4 av;
        if (gr < M) {
            av = *(const float4*)(A + (size_t)gr * K + k0 + ahalf);
        } else {
            av = make_float4(0.f, 0.f, 0.f, 0.f);
        }
        float4 wv = *(const float4*)(W + (size_t)(k0 + wk) * N + colBase + wc);

        __syncthreads();
        As[ahalf + 0][ar] = av.x;
        As[ahalf + 1][ar] = av.y;
        As[ahalf + 2][ar] = av.z;
        As[ahalf + 3][ar] = av.w;
        *(float4*)&Ws[wk][wc] = wv;
        __syncthreads();

#pragma unroll
        for (int kk = 0; kk < 8; kk++) {
            float4 a0 = *(const float4*)&As[kk][ty * 4];
            float4 a1 = *(const float4*)&As[kk][64 + ty * 4];
            float4 b0 = *(const float4*)&Ws[kk][tx * 4];
            float4 b1 = *(const float4*)&Ws[kk][64 + tx * 4];
            float ra[8] = {a0.x, a0.y, a0.z, a0.w, a1.x, a1.y, a1.z, a1.w};
            float rb[8] = {b0.x, b0.y, b0.z, b0.w, b1.x, b1.y, b1.z, b1.w};
#pragma unroll
            for (int i = 0; i < 8; i++)
#pragma unroll
                for (int j = 0; j < 8; j++)
                    acc[i][j] = fmaf(ra[i], rb[j], acc[i][j]);
        }
    }

    // Epilogue
    const int c0 = colBase + tx * 4;
    const int c1 = colBase + 64 + tx * 4;
    float4 bv0 = make_float4(0.f, 0.f, 0.f, 0.f), bv1 = bv0;
    if (EPI != EPI_NOBIAS) {
        bv0 = *(const float4*)(bias + c0);
        bv1 = *(const float4*)(bias + c1);
    }

#pragma unroll
    for (int i = 0; i < 8; i++) {
        int lr = (i < 4) ? (ty * 4 + i) : (64 + ty * 4 + i - 4);
        int gr = rowBase + lr;
        if (gr >= M) continue;
        float v[8];
#pragma unroll
        for (int j = 0; j < 8; j++) v[j] = acc[i][j];
        if (EPI != EPI_NOBIAS) {
            v[0] += bv0.x; v[1] += bv0.y; v[2] += bv0.z; v[3] += bv0.w;
            v[4] += bv1.x; v[5] += bv1.y; v[6] += bv1.z; v[7] += bv1.w;
        }
        if (EPI == EPI_BIAS_GELU) {
#pragma unroll
            for (int j = 0; j < 8; j++) v[j] = gelu_tanh(v[j]);
        }
        if (EPI == EPI_BIAS_RES) {
            float4 r0 = *(const float4*)(res + (size_t)gr * N + c0);
            float4 r1 = *(const float4*)(res + (size_t)gr * N + c1);
            v[0] += r0.x; v[1] += r0.y; v[2] += r0.z; v[3] += r0.w;
            v[4] += r1.x; v[5] += r1.y; v[6] += r1.z; v[7] += r1.w;
        }
        *(float4*)(C + (size_t)gr * N + c0) = make_float4(v[0], v[1], v[2], v[3]);
        *(float4*)(C + (size_t)gr * N + c1) = make_float4(v[4], v[5], v[6], v[7]);
    }
}

// ---------------------------------------------------------------------------
// adaLN modulation: g_mod[b, 0:6D] = silu(c[b]) @ W_ada + b_ada
// grid (6D/256, B), 256 threads
// ---------------------------------------------------------------------------
__global__ void __launch_bounds__(256) mod_kernel(
    const float* __restrict__ c, const float* __restrict__ W,
    const float* __restrict__ bias)
{
    const int b = blockIdx.y;
    const int col = blockIdx.x * 256 + threadIdx.x;
    __shared__ float sc[DM];
    for (int i = threadIdx.x; i < DM; i += 256) {
        float v = c[b * DM + i];
        sc[i] = v / (1.0f + __expf(-v));
    }
    __syncthreads();
    float acc = 0.0f;
#pragma unroll 8
    for (int k = 0; k < DM; k++)
        acc = fmaf(sc[k], W[(size_t)k * (6 * DM) + col], acc);
    g_mod[b * 6 * DM + col] = acc + bias[col];
}

// ---------------------------------------------------------------------------
// LayerNorm + modulate: out[row] = LN(x[row])*(1+scale[b]) + shift[b]
// one block (256 threads) per row; 4 elems per thread via float4
// ---------------------------------------------------------------------------
__global__ void __launch_bounds__(256) lnmod_kernel(
    const float* __restrict__ x, int shOff, int scOff, float* __restrict__ out)
{
    const int row = blockIdx.x;
    const int b = row >> 10;
    const int tid = threadIdx.x;

    float4 v = ((const float4*)(x + (size_t)row * DM))[tid];
    float s  = v.x + v.y + v.z + v.w;
    float s2 = v.x * v.x + v.y * v.y + v.z * v.z + v.w * v.w;

    __shared__ float red[16];
#pragma unroll
    for (int off = 16; off > 0; off >>= 1) {
        s  += __shfl_xor_sync(0xffffffffu, s,  off);
        s2 += __shfl_xor_sync(0xffffffffu, s2, off);
    }
    const int warp = tid >> 5, lane = tid & 31;
    if (lane == 0) { red[warp] = s; red[warp + 8] = s2; }
    __syncthreads();
    if (tid == 0) {
        float ts = 0.f, ts2 = 0.f;
#pragma unroll
        for (int i = 0; i < 8; i++) { ts += red[i]; ts2 += red[i + 8]; }
        float mu  = ts * (1.0f / DM);
        float var = ts2 * (1.0f / DM) - mu * mu;
        red[0] = mu;
        red[1] = rsqrtf(var + 1e-6f);
    }
    __syncthreads();
    const float mu = red[0], rs = red[1];

    const float* modp = g_mod + b * 6 * DM;
    const int cc = tid * 4;
    float4 sh  = *(const float4*)(modp + shOff + cc);
    float4 scv = *(const float4*)(modp + scOff + cc);
    float4 o;
    o.x = (v.x - mu) * rs * (1.0f + scv.x) + sh.x;
    o.y = (v.y - mu) * rs * (1.0f + scv.y) + sh.y;
    o.z = (v.z - mu) * rs * (1.0f + scv.z) + sh.z;
    o.w = (v.w - mu) * rs * (1.0f + scv.w) + sh.w;
    ((float4*)(out + (size_t)row * DM))[tid] = o;
}

// ---------------------------------------------------------------------------
// Self-attention (flash-style, online softmax).
// grid (N/64, H, B), 64 threads; each thread = one query row.
// qkv layout: [token, 3*DM]; q at +0, k at +DM, v at +2*DM; head h at +h*64.
// Writes g_attn[token, h*64+d].
// Smem transposed [d][j] / [j][tid] for conflict-free access. 48KB exactly.
// ---------------------------------------------------------------------------
__global__ void __launch_bounds__(64) self_attn_kernel()
{
    __shared__ float Kt[64][64];   // [d][key]
    __shared__ float Vt[64][64];   // [d][key]
    __shared__ float St[64][64];   // [key][query-thread]

    const int qt = blockIdx.x, h = blockIdx.y, b = blockIdx.z;
    const int tid = threadIdx.x;
    const int qrow = b * NSEQ + qt * 64 + tid;

    float q[64], o[64];
    {
        const float4* qp = (const float4*)(g_qkv + (size_t)qrow * (3 * DM) + h * 64);
#pragma unroll
        for (int i = 0; i < 16; i++) {
            float4 t = qp[i];
            q[4 * i + 0] = t.x * 0.125f;
            q[4 * i + 1] = t.y * 0.125f;
            q[4 * i + 2] = t.z * 0.125f;
            q[4 * i + 3] = t.w * 0.125f;
        }
    }
#pragma unroll
    for (int d = 0; d < 64; d++) o[d] = 0.0f;
    float m = -1e30f, l = 0.0f;

    for (int kt = 0; kt < 16; kt++) {
        __syncthreads();
        const size_t krow = (size_t)(b * NSEQ + kt * 64 + tid) * (3 * DM);
        const float4* kp = (const float4*)(g_qkv + krow + DM + h * 64);
        const float4* vp = (const float4*)(g_qkv + krow + 2 * DM + h * 64);
#pragma unroll
        for (int i = 0; i < 16; i++) {
            float4 kv = kp[i];
            float4 vv = vp[i];
            Kt[4 * i + 0][tid] = kv.x; Kt[4 * i + 1][tid] = kv.y;
            Kt[4 * i + 2][tid] = kv.z; Kt[4 * i + 3][tid] = kv.w;
            Vt[4 * i + 0][tid] = vv.x; Vt[4 * i + 1][tid] = vv.y;
            Vt[4 * i + 2][tid] = vv.z; Vt[4 * i + 3][tid] = vv.w;
        }
        __syncthreads();

        float tmax = -1e30f;
#pragma unroll 4
        for (int j = 0; j < 64; j++) {
            float s = 0.0f;
#pragma unroll
            for (int d = 0; d < 64; d++) s = fmaf(q[d], Kt[d][j], s);
            St[j][tid] = s;
            tmax = fmaxf(tmax, s);
        }
        float mnew = fmaxf(m, tmax);
        float corr = __expf(m - mnew);
        l *= corr;
#pragma unroll
        for (int d = 0; d < 64; d++) o[d] *= corr;
#pragma unroll 2
        for (int j = 0; j < 64; j++) {
            float p = __expf(St[j][tid] - mnew);
            l += p;
#pragma unroll
            for (int d = 0; d < 64; d++) o[d] = fmaf(p, Vt[d][j], o[d]);
        }
        m = mnew;
    }

    const float inv = 1.0f / l;
    float4* op = (float4*)(g_attn + (size_t)qrow * DM + h * 64);
#pragma unroll
    for (int i = 0; i < 16; i++)
        op[i] = make_float4(o[4 * i + 0] * inv, o[4 * i + 1] * inv,
                            o[4 * i + 2] * inv, o[4 * i + 3] * inv);
}

// ---------------------------------------------------------------------------
// Cross-attention: 77 keys per (b,h). Two-pass softmax (no score storage).
// grid (N/64, H, B), 64 threads; each thread = one query row.
// ---------------------------------------------------------------------------
__global__ void __launch_bounds__(64) cross_attn_kernel()
{
    __shared__ float Kt[64][TL + 3];   // [d][l]
    __shared__ float Vt[64][TL + 3];

    const int qt = blockIdx.x, h = blockIdx.y, b = blockIdx.z;
    const int tid = threadIdx.x;

    for (int i = tid; i < TL * 64; i += 64) {
        const int l = i >> 6;
        const int d = i & 63;
        const size_t src = (size_t)(b * TL + l) * DM + h * 64 + d;
        Kt[d][l] = g_kc[src];
        Vt[d][l] = g_vc[src];
    }
    __syncthreads();

    const int row = b * NSEQ + qt * 64 + tid;
    float q[64];
    {
        const float4* qp = (const float4*)(g_qb + (size_t)row * DM + h * 64);
#pragma unroll
        for (int i = 0; i < 16; i++) {
            float4 t = qp[i];
            q[4 * i + 0] = t.x * 0.125f;
            q[4 * i + 1] = t.y * 0.125f;
            q[4 * i + 2] = t.z * 0.125f;
            q[4 * i + 3] = t.w * 0.125f;
        }
    }

    float m = -1e30f;
    for (int l = 0; l < TL; l++) {
        float s = 0.0f;
#pragma unroll
        for (int d = 0; d < 64; d++) s = fmaf(q[d], Kt[d][l], s);
        m = fmaxf(m, s);
    }

    float o[64];
#pragma unroll
    for (int d = 0; d < 64; d++) o[d] = 0.0f;
    float lsum = 0.0f;
    for (int l = 0; l < TL; l++) {
        float s = 0.0f;
#pragma unroll
        for (int d = 0; d < 64; d++) s = fmaf(q[d], Kt[d][l], s);
        float p = __expf(s - m);
        lsum += p;
#pragma unroll
        for (int d = 0; d < 64; d++) o[d] = fmaf(p, Vt[d][l], o[d]);
    }

    const float inv = 1.0f / lsum;
    float4* op = (float4*)(g_attn + (size_t)row * DM + h * 64);
#pragma unroll
    for (int i = 0; i < 16; i++)
        op[i] = make_float4(o[4 * i + 0] * inv, o[4 * i + 1] * inv,
                            o[4 * i + 2] * inv, o[4 * i + 3] * inv);
}

// ---------------------------------------------------------------------------
// Host side
// ---------------------------------------------------------------------------
template <int EPI>
static void launch_gemm(const float* A, const float* W, const float* bias,
                        const float* res, float* C, int M, int N, int K)
{
    dim3 grid(N / 128, (M + 127) / 128);
    sgemm_kernel<EPI><<<grid, 256>>>(A, W, bias, res, C, M, N, K);
}

extern "C" void kernel_launch(void* const* d_in, const int* in_sizes, int n_in,
                              void* d_out, int out_size)
{
    const float* x       = (const float*)d_in[0];
    const float* c       = (const float*)d_in[1];
    const float* text    = (const float*)d_in[2];
    const float* W_ada   = (const float*)d_in[3];
    const float* b_ada   = (const float*)d_in[4];
    const float* W_qkv   = (const float*)d_in[5];
    const float* b_qkv   = (const float*)d_in[6];
    const float* W_proj  = (const float*)d_in[7];
    const float* b_proj  = (const float*)d_in[8];
    const float* W_ctx   = (const float*)d_in[9];
    const float* b_ctx   = (const float*)d_in[10];
    const float* W_q     = (const float*)d_in[11];
    const float* W_k     = (const float*)d_in[12];
    const float* W_v     = (const float*)d_in[13];
    const float* W_out   = (const float*)d_in[14];
    const float* b_out   = (const float*)d_in[15];
    const float* W_fc1   = (const float*)d_in[16];
    const float* b_fc1   = (const float*)d_in[17];
    const float* W_fc2   = (const float*)d_in[18];
    const float* b_fc2   = (const float*)d_in[19];
    float* out = (float*)d_out;

    float *p_h, *p_qkv, *p_attn, *p_x1, *p_x2, *p_ctx, *p_qb, *p_kc, *p_vc, *p_hidden;
    cudaGetSymbolAddress((void**)&p_h,      g_h);
    cudaGetSymbolAddress((void**)&p_qkv,    g_qkv);
    cudaGetSymbolAddress((void**)&p_attn,   g_attn);
    cudaGetSymbolAddress((void**)&p_x1,     g_x1);
    cudaGetSymbolAddress((void**)&p_x2,     g_x2);
    cudaGetSymbolAddress((void**)&p_ctx,    g_ctx);
    cudaGetSymbolAddress((void**)&p_qb,     g_qb);
    cudaGetSymbolAddress((void**)&p_kc,     g_kc);
    cudaGetSymbolAddress((void**)&p_vc,     g_vc);
    cudaGetSymbolAddress((void**)&p_hidden, g_hidden);

    // 1. adaLN modulation
    {
        dim3 grid(6 * DM / 256, BB);
        mod_kernel<<<grid, 256>>>(c, W_ada, b_ada);
    }

    // --- self-attention block ---
    lnmod_kernel<<<TTOK, 256>>>(x, 0 * DM, 1 * DM, p_h);
    launch_gemm<EPI_BIAS>(p_h, W_qkv, b_qkv, nullptr, p_qkv, TTOK, 3 * DM, DM);
    {
        dim3 grid(NSEQ / 64, NH, BB);
        self_attn_kernel<<<grid, 64>>>();
    }
    launch_gemm<EPI_BIAS_RES>(p_attn, W_proj, b_proj, x, p_x1, TTOK, DM, DM);

    // --- cross-attention block ---
    lnmod_kernel<<<TTOK, 256>>>(p_x1, 2 * DM, 3 * DM, p_h);
    launch_gemm<EPI_BIAS>(text, W_ctx, b_ctx, nullptr, p_ctx, TCTX, DM, TD);
    launch_gemm<EPI_NOBIAS>(p_h, W_q, nullptr, nullptr, p_qb, TTOK, DM, DM);
    launch_gemm<EPI_NOBIAS>(p_ctx, W_k, nullptr, nullptr, p_kc, TCTX, DM, DM);
    launch_gemm<EPI_NOBIAS>(p_ctx, W_v, nullptr, nullptr, p_vc, TCTX, DM, DM);
    {
        dim3 grid(NSEQ / 64, NH, BB);
        cross_attn_kernel<<<grid, 64>>>();
    }
    launch_gemm<EPI_BIAS_RES>(p_attn, W_out, b_out, p_x1, p_x2, TTOK, DM, DM);

    // --- MLP block ---
    lnmod_kernel<<<TTOK, 256>>>(p_x2, 4 * DM, 5 * DM, p_h);
    launch_gemm<EPI_BIAS_GELU>(p_h, W_fc1, b_fc1, nullptr, p_hidden, TTOK, 4 * DM, DM);
    launch_gemm<EPI_BIAS_RES>(p_hidden, W_fc2, b_fc2, p_x2, out, TTOK, DM, 4 * DM);
}

// round 3
// speedup vs baseline: 1.9244x; 1.9244x over previous
#include <cuda_runtime.h>
#include <math.h>
#include <stdint.h>

// ---------------------------------------------------------------------------
// Problem constants
// ---------------------------------------------------------------------------
#define BB 4
#define NSEQ 1024
#define DM 1024
#define NH 16
#define HD 64
#define TD 768
#define TL 77
#define TTOK (BB * NSEQ)   // 4096
#define TCTX (BB * TL)     // 308

// ---------------------------------------------------------------------------
// Scratch (static device globals; no allocation allowed)
// ---------------------------------------------------------------------------
__device__ float g_mod[BB * 6 * DM];
__device__ float g_h[TTOK * DM];
__device__ float g_qkv[TTOK * 3 * DM];
__device__ float g_attn[TTOK * DM];
__device__ float g_x1[TTOK * DM];
__device__ float g_x2[TTOK * DM];
__device__ float g_ctx[TCTX * DM];
__device__ float g_qb[TTOK * DM];
__device__ float g_kc[TCTX * DM];
__device__ float g_vc[TCTX * DM];
__device__ float g_hidden[TTOK * 4 * DM];

// ---------------------------------------------------------------------------
// Helpers
// ---------------------------------------------------------------------------
__device__ __forceinline__ float gelu_tanh(float x) {
    float x3 = x * x * x;
    float t  = tanhf(0.7978845608028654f * (x + 0.044715f * x3));
    return 0.5f * x * (1.0f + t);
}

__device__ __forceinline__ uint32_t f2tf32(float f) {
    uint32_t u;
    asm("cvt.rna.tf32.f32 %0, %1;" : "=r"(u) : "f"(f));
    return u;
}

__device__ __forceinline__ void mma1688(float* c, const uint32_t* a, const uint32_t* b) {
    asm volatile(
        "mma.sync.aligned.m16n8k8.row.col.f32.tf32.tf32.f32 "
        "{%0,%1,%2,%3}, {%4,%5,%6,%7}, {%8,%9}, {%0,%1,%2,%3};"
        : "+f"(c[0]), "+f"(c[1]), "+f"(c[2]), "+f"(c[3])
        : "r"(a[0]), "r"(a[1]), "r"(a[2]), "r"(a[3]), "r"(b[0]), "r"(b[1]));
}

// Epilogue modes
#define EPI_BIAS      0
#define EPI_BIAS_GELU 1
#define EPI_BIAS_RES  2
#define EPI_NOBIAS    3

// ---------------------------------------------------------------------------
// TF32 tensor-core GEMM: C[M,N] = A[M,K] @ W[K,N] (+bias)(+gelu)(+residual)
// BM=128, BN=128, BK=16, 256 threads (8 warps: 4 over M x 2 over N).
// Each warp: 32x64 via m16n8k8 (2 m-tiles x 8 n-tiles).
// N % 128 == 0, K % 16 == 0 required (true for all call sites). M guarded.
// ---------------------------------------------------------------------------
template <int EPI>
__global__ void __launch_bounds__(256) tgemm_kernel(
    const float* __restrict__ A, const float* __restrict__ W,
    const float* __restrict__ bias, const float* __restrict__ res,
    float* __restrict__ C, int M, int N, int K)
{
    __shared__ uint32_t As[128][20];   // [m][k] tf32 bits, pad 20 -> conflict-free frag reads
    __shared__ uint32_t Bs[16][136];   // [k][n] tf32 bits, pad 136 -> conflict-free frag reads

    const int tid  = threadIdx.x;
    const int lane = tid & 31;
    const int warp = tid >> 5;
    const int g = lane >> 2;
    const int t = lane & 3;
    const int wm = (warp & 3) * 32;
    const int wn = (warp >> 2) * 64;
    const int rowBase = blockIdx.y * 128;
    const int colBase = blockIdx.x * 128;

    // gmem->smem mapping
    const int arow = tid >> 2;            // 0..63 (also +64)
    const int acol = (tid & 3) * 4;       // 0,4,8,12
    const int wk   = tid >> 5;            // 0..7 (also +8)
    const int wn4  = (tid & 31) * 4;      // 0..124

    float acc[2][8][4];
#pragma unroll
    for (int mt = 0; mt < 2; mt++)
#pragma unroll
        for (int nt = 0; nt < 8; nt++)
#pragma unroll
            for (int i = 0; i < 4; i++) acc[mt][nt][i] = 0.0f;

    float4 aR0, aR1, wR0, wR1;

    // prologue load (k0 = 0)
    {
        const int r0 = rowBase + arow, r1 = r0 + 64;
        aR0 = (r0 < M) ? *(const float4*)(A + (size_t)r0 * K + acol)
                       : make_float4(0.f, 0.f, 0.f, 0.f);
        aR1 = (r1 < M) ? *(const float4*)(A + (size_t)r1 * K + acol)
                       : make_float4(0.f, 0.f, 0.f, 0.f);
        wR0 = *(const float4*)(W + (size_t)wk       * N + colBase + wn4);
        wR1 = *(const float4*)(W + (size_t)(wk + 8) * N + colBase + wn4);
    }
    {
        As[arow][acol + 0] = f2tf32(aR0.x); As[arow][acol + 1] = f2tf32(aR0.y);
        As[arow][acol + 2] = f2tf32(aR0.z); As[arow][acol + 3] = f2tf32(aR0.w);
        As[arow + 64][acol + 0] = f2tf32(aR1.x); As[arow + 64][acol + 1] = f2tf32(aR1.y);
        As[arow + 64][acol + 2] = f2tf32(aR1.z); As[arow + 64][acol + 3] = f2tf32(aR1.w);
        uint4 b0 = make_uint4(f2tf32(wR0.x), f2tf32(wR0.y), f2tf32(wR0.z), f2tf32(wR0.w));
        uint4 b1 = make_uint4(f2tf32(wR1.x), f2tf32(wR1.y), f2tf32(wR1.z), f2tf32(wR1.w));
        *(uint4*)&Bs[wk][wn4]     = b0;
        *(uint4*)&Bs[wk + 8][wn4] = b1;
    }
    __syncthreads();

    for (int k0 = 0; k0 < K; k0 += 16) {
        const bool hasNext = (k0 + 16) < K;
        if (hasNext) {
            const int kn = k0 + 16;
            const int r0 = rowBase + arow, r1 = r0 + 64;
            aR0 = (r0 < M) ? *(const float4*)(A + (size_t)r0 * K + kn + acol)
                           : make_float4(0.f, 0.f, 0.f, 0.f);
            aR1 = (r1 < M) ? *(const float4*)(A + (size_t)r1 * K + kn + acol)
                           : make_float4(0.f, 0.f, 0.f, 0.f);
            wR0 = *(const float4*)(W + (size_t)(kn + wk)     * N + colBase + wn4);
            wR1 = *(const float4*)(W + (size_t)(kn + wk + 8) * N + colBase + wn4);
        }

#pragma unroll
        for (int ks = 0; ks < 16; ks += 8) {
            uint32_t af[2][4];
            uint32_t bf[8][2];
#pragma unroll
            for (int mt = 0; mt < 2; mt++) {
                const int m = wm + mt * 16;
                af[mt][0] = As[m + g][ks + t];
                af[mt][1] = As[m + g + 8][ks + t];
                af[mt][2] = As[m + g][ks + t + 4];
                af[mt][3] = As[m + g + 8][ks + t + 4];
            }
#pragma unroll
            for (int nt = 0; nt < 8; nt++) {
                const int n = wn + nt * 8;
                bf[nt][0] = Bs[ks + t][n + g];
                bf[nt][1] = Bs[ks + t + 4][n + g];
            }
#pragma unroll
            for (int mt = 0; mt < 2; mt++)
#pragma unroll
                for (int nt = 0; nt < 8; nt++)
                    mma1688(acc[mt][nt], af[mt], bf[nt]);
        }
        __syncthreads();

        if (hasNext) {
            As[arow][acol + 0] = f2tf32(aR0.x); As[arow][acol + 1] = f2tf32(aR0.y);
            As[arow][acol + 2] = f2tf32(aR0.z); As[arow][acol + 3] = f2tf32(aR0.w);
            As[arow + 64][acol + 0] = f2tf32(aR1.x); As[arow + 64][acol + 1] = f2tf32(aR1.y);
            As[arow + 64][acol + 2] = f2tf32(aR1.z); As[arow + 64][acol + 3] = f2tf32(aR1.w);
            uint4 b0 = make_uint4(f2tf32(wR0.x), f2tf32(wR0.y), f2tf32(wR0.z), f2tf32(wR0.w));
            uint4 b1 = make_uint4(f2tf32(wR1.x), f2tf32(wR1.y), f2tf32(wR1.z), f2tf32(wR1.w));
            *(uint4*)&Bs[wk][wn4]     = b0;
            *(uint4*)&Bs[wk + 8][wn4] = b1;
            __syncthreads();
        }
    }

    // Epilogue
#pragma unroll
    for (int mt = 0; mt < 2; mt++) {
        const int row0 = rowBase + wm + mt * 16 + g;
        const int row1 = row0 + 8;
#pragma unroll
        for (int nt = 0; nt < 8; nt++) {
            const int col = colBase + wn + nt * 8 + t * 2;
            float b0 = 0.f, b1 = 0.f;
            if (EPI != EPI_NOBIAS) { b0 = bias[col]; b1 = bias[col + 1]; }
            float v0 = acc[mt][nt][0] + b0;
            float v1 = acc[mt][nt][1] + b1;
            float v2 = acc[mt][nt][2] + b0;
            float v3 = acc[mt][nt][3] + b1;
            if (EPI == EPI_BIAS_GELU) {
                v0 = gelu_tanh(v0); v1 = gelu_tanh(v1);
                v2 = gelu_tanh(v2); v3 = gelu_tanh(v3);
            }
            if (row0 < M) {
                if (EPI == EPI_BIAS_RES) {
                    float2 r = *(const float2*)(res + (size_t)row0 * N + col);
                    v0 += r.x; v1 += r.y;
                }
                *(float2*)(C + (size_t)row0 * N + col) = make_float2(v0, v1);
            }
            if (row1 < M) {
                if (EPI == EPI_BIAS_RES) {
                    float2 r = *(const float2*)(res + (size_t)row1 * N + col);
                    v2 += r.x; v3 += r.y;
                }
                *(float2*)(C + (size_t)row1 * N + col) = make_float2(v2, v3);
            }
        }
    }
}

// ---------------------------------------------------------------------------
// adaLN modulation: g_mod[b, 0:6D] = silu(c[b]) @ W_ada + b_ada
// ---------------------------------------------------------------------------
__global__ void __launch_bounds__(256) mod_kernel(
    const float* __restrict__ c, const float* __restrict__ W,
    const float* __restrict__ bias)
{
    const int b = blockIdx.y;
    const int col = blockIdx.x * 256 + threadIdx.x;
    __shared__ float sc[DM];
    for (int i = threadIdx.x; i < DM; i += 256) {
        float v = c[b * DM + i];
        sc[i] = v / (1.0f + __expf(-v));
    }
    __syncthreads();
    float acc = 0.0f;
#pragma unroll 8
    for (int k = 0; k < DM; k++)
        acc = fmaf(sc[k], W[(size_t)k * (6 * DM) + col], acc);
    g_mod[b * 6 * DM + col] = acc + bias[col];
}

// ---------------------------------------------------------------------------
// LayerNorm + modulate
// ---------------------------------------------------------------------------
__global__ void __launch_bounds__(256) lnmod_kernel(
    const float* __restrict__ x, int shOff, int scOff, float* __restrict__ out)
{
    const int row = blockIdx.x;
    const int b = row >> 10;
    const int tid = threadIdx.x;

    float4 v = ((const float4*)(x + (size_t)row * DM))[tid];
    float s  = v.x + v.y + v.z + v.w;
    float s2 = v.x * v.x + v.y * v.y + v.z * v.z + v.w * v.w;

    __shared__ float red[16];
#pragma unroll
    for (int off = 16; off > 0; off >>= 1) {
        s  += __shfl_xor_sync(0xffffffffu, s,  off);
        s2 += __shfl_xor_sync(0xffffffffu, s2, off);
    }
    const int warp = tid >> 5, lane = tid & 31;
    if (lane == 0) { red[warp] = s; red[warp + 8] = s2; }
    __syncthreads();
    if (tid == 0) {
        float ts = 0.f, ts2 = 0.f;
#pragma unroll
        for (int i = 0; i < 8; i++) { ts += red[i]; ts2 += red[i + 8]; }
        float mu  = ts * (1.0f / DM);
        float var = ts2 * (1.0f / DM) - mu * mu;
        red[0] = mu;
        red[1] = rsqrtf(var + 1e-6f);
    }
    __syncthreads();
    const float mu = red[0], rs = red[1];

    const float* modp = g_mod + b * 6 * DM;
    const int cc = tid * 4;
    float4 sh  = *(const float4*)(modp + shOff + cc);
    float4 scv = *(const float4*)(modp + scOff + cc);
    float4 o;
    o.x = (v.x - mu) * rs * (1.0f + scv.x) + sh.x;
    o.y = (v.y - mu) * rs * (1.0f + scv.y) + sh.y;
    o.z = (v.z - mu) * rs * (1.0f + scv.z) + sh.z;
    o.w = (v.w - mu) * rs * (1.0f + scv.w) + sh.w;
    ((float4*)(out + (size_t)row * DM))[tid] = o;
}

// ---------------------------------------------------------------------------
// Self-attention (flash-style). grid (N/64, H, B), 64 threads = 64 queries.
// K/V tiles stored row-major [j][d] -> per-thread float4 LDS (warp broadcast),
// 4 FMAs per LDS.128, 4 partial accumulators for ILP.
// ---------------------------------------------------------------------------
__global__ void __launch_bounds__(64) self_attn_kernel()
{
    __shared__ float Ks[64][64];
    __shared__ float Vs[64][64];
    __shared__ float St[64][64];   // [j][query-thread]

    const int qt = blockIdx.x, h = blockIdx.y, b = blockIdx.z;
    const int tid = threadIdx.x;
    const int qrow = b * NSEQ + qt * 64 + tid;

    float q[64], o[64];
    {
        const float4* qp = (const float4*)(g_qkv + (size_t)qrow * (3 * DM) + h * 64);
#pragma unroll
        for (int i = 0; i < 16; i++) {
            float4 tq = qp[i];
            q[4 * i + 0] = tq.x * 0.125f;
            q[4 * i + 1] = tq.y * 0.125f;
            q[4 * i + 2] = tq.z * 0.125f;
            q[4 * i + 3] = tq.w * 0.125f;
        }
    }
#pragma unroll
    for (int d = 0; d < 64; d++) o[d] = 0.0f;
    float m = -1e30f, l = 0.0f;

    for (int kt = 0; kt < 16; kt++) {
        __syncthreads();
        const size_t krow = (size_t)(b * NSEQ + kt * 64 + tid) * (3 * DM);
        const float4* kp = (const float4*)(g_qkv + krow + DM + h * 64);
        const float4* vp = (const float4*)(g_qkv + krow + 2 * DM + h * 64);
        float4* kd = (float4*)Ks[tid];
        float4* vd = (float4*)Vs[tid];
#pragma unroll
        for (int i = 0; i < 16; i++) { kd[i] = kp[i]; vd[i] = vp[i]; }
        __syncthreads();

        float tmax = -1e30f;
#pragma unroll 2
        for (int j = 0; j < 64; j++) {
            const float4* kr = (const float4*)Ks[j];
            float s0 = 0.f, s1 = 0.f, s2 = 0.f, s3 = 0.f;
#pragma unroll
            for (int i = 0; i < 16; i++) {
                float4 kv = kr[i];
                s0 = fmaf(q[4 * i + 0], kv.x, s0);
                s1 = fmaf(q[4 * i + 1], kv.y, s1);
                s2 = fmaf(q[4 * i + 2], kv.z, s2);
                s3 = fmaf(q[4 * i + 3], kv.w, s3);
            }
            float s = (s0 + s1) + (s2 + s3);
            St[j][tid] = s;
            tmax = fmaxf(tmax, s);
        }
        const float mnew = fmaxf(m, tmax);
        const float corr = __expf(m - mnew);
        l *= corr;
#pragma unroll
        for (int d = 0; d < 64; d++) o[d] *= corr;
#pragma unroll 2
        for (int j = 0; j < 64; j++) {
            const float p = __expf(St[j][tid] - mnew);
            l += p;
            const float4* vr = (const float4*)Vs[j];
#pragma unroll
            for (int i = 0; i < 16; i++) {
                float4 vv = vr[i];
                o[4 * i + 0] = fmaf(p, vv.x, o[4 * i + 0]);
                o[4 * i + 1] = fmaf(p, vv.y, o[4 * i + 1]);
                o[4 * i + 2] = fmaf(p, vv.z, o[4 * i + 2]);
                o[4 * i + 3] = fmaf(p, vv.w, o[4 * i + 3]);
            }
        }
        m = mnew;
    }

    const float inv = 1.0f / l;
    float4* op = (float4*)(g_attn + (size_t)qrow * DM + h * 64);
#pragma unroll
    for (int i = 0; i < 16; i++)
        op[i] = make_float4(o[4 * i + 0] * inv, o[4 * i + 1] * inv,
                            o[4 * i + 2] * inv, o[4 * i + 3] * inv);
}

// ---------------------------------------------------------------------------
// Cross-attention: 77 keys. Two-pass softmax. Row-major K/V tiles + float4.
// ---------------------------------------------------------------------------
__global__ void __launch_bounds__(64) cross_attn_kernel()
{
    __shared__ float Kc[TL][64];
    __shared__ float Vc[TL][64];

    const int qt = blockIdx.x, h = blockIdx.y, b = blockIdx.z;
    const int tid = threadIdx.x;

    for (int i = tid; i < TL * 16; i += 64) {
        const int l = i >> 4;
        const int c4 = (i & 15);
        const size_t src = (size_t)(b * TL + l) * DM + h * 64 + c4 * 4;
        ((float4*)Kc[l])[c4] = *(const float4*)(g_kc + src);
        ((float4*)Vc[l])[c4] = *(const float4*)(g_vc + src);
    }
    __syncthreads();

    const int row = b * NSEQ + qt * 64 + tid;
    float q[64];
    {
        const float4* qp = (const float4*)(g_qb + (size_t)row * DM + h * 64);
#pragma unroll
        for (int i = 0; i < 16; i++) {
            float4 tq = qp[i];
            q[4 * i + 0] = tq.x * 0.125f;
            q[4 * i + 1] = tq.y * 0.125f;
            q[4 * i + 2] = tq.z * 0.125f;
            q[4 * i + 3] = tq.w * 0.125f;
        }
    }

    float m = -1e30f;
    for (int l = 0; l < TL; l++) {
        const float4* kr = (const float4*)Kc[l];
        float s0 = 0.f, s1 = 0.f, s2 = 0.f, s3 = 0.f;
#pragma unroll
        for (int i = 0; i < 16; i++) {
            float4 kv = kr[i];
            s0 = fmaf(q[4 * i + 0], kv.x, s0);
            s1 = fmaf(q[4 * i + 1], kv.y, s1);
            s2 = fmaf(q[4 * i + 2], kv.z, s2);
            s3 = fmaf(q[4 * i + 3], kv.w, s3);
        }
        m = fmaxf(m, (s0 + s1) + (s2 + s3));
    }

    float o[64];
#pragma unroll
    for (int d = 0; d < 64; d++) o[d] = 0.0f;
    float lsum = 0.0f;
    for (int l = 0; l < TL; l++) {
        const float4* kr = (const float4*)Kc[l];
        float s0 = 0.f, s1 = 0.f, s2 = 0.f, s3 = 0.f;
#pragma unroll
        for (int i = 0; i < 16; i++) {
            float4 kv = kr[i];
            s0 = fmaf(q[4 * i + 0], kv.x, s0);
            s1 = fmaf(q[4 * i + 1], kv.y, s1);
            s2 = fmaf(q[4 * i + 2], kv.z, s2);
            s3 = fmaf(q[4 * i + 3], kv.w, s3);
        }
        const float p = __expf((s0 + s1) + (s2 + s3) - m);
        lsum += p;
        const float4* vr = (const float4*)Vc[l];
#pragma unroll
        for (int i = 0; i < 16; i++) {
            float4 vv = vr[i];
            o[4 * i + 0] = fmaf(p, vv.x, o[4 * i + 0]);
            o[4 * i + 1] = fmaf(p, vv.y, o[4 * i + 1]);
            o[4 * i + 2] = fmaf(p, vv.z, o[4 * i + 2]);
            o[4 * i + 3] = fmaf(p, vv.w, o[4 * i + 3]);
        }
    }

    const float inv = 1.0f / lsum;
    float4* op = (float4*)(g_attn + (size_t)row * DM + h * 64);
#pragma unroll
    for (int i = 0; i < 16; i++)
        op[i] = make_float4(o[4 * i + 0] * inv, o[4 * i + 1] * inv,
                            o[4 * i + 2] * inv, o[4 * i + 3] * inv);
}

// ---------------------------------------------------------------------------
// Host side
// ---------------------------------------------------------------------------
template <int EPI>
static void launch_gemm(const float* A, const float* W, const float* bias,
                        const float* res, float* C, int M, int N, int K)
{
    dim3 grid(N / 128, (M + 127) / 128);
    tgemm_kernel<EPI><<<grid, 256>>>(A, W, bias, res, C, M, N, K);
}

extern "C" void kernel_launch(void* const* d_in, const int* in_sizes, int n_in,
                              void* d_out, int out_size)
{
    const float* x       = (const float*)d_in[0];
    const float* c       = (const float*)d_in[1];
    const float* text    = (const float*)d_in[2];
    const float* W_ada   = (const float*)d_in[3];
    const float* b_ada   = (const float*)d_in[4];
    const float* W_qkv   = (const float*)d_in[5];
    const float* b_qkv   = (const float*)d_in[6];
    const float* W_proj  = (const float*)d_in[7];
    const float* b_proj  = (const float*)d_in[8];
    const float* W_ctx   = (const float*)d_in[9];
    const float* b_ctx   = (const float*)d_in[10];
    const float* W_q     = (const float*)d_in[11];
    const float* W_k     = (const float*)d_in[12];
    const float* W_v     = (const float*)d_in[13];
    const float* W_out   = (const float*)d_in[14];
    const float* b_out   = (const float*)d_in[15];
    const float* W_fc1   = (const float*)d_in[16];
    const float* b_fc1   = (const float*)d_in[17];
    const float* W_fc2   = (const float*)d_in[18];
    const float* b_fc2   = (const float*)d_in[19];
    float* out = (float*)d_out;

    float *p_h, *p_qkv, *p_attn, *p_x1, *p_x2, *p_ctx, *p_qb, *p_kc, *p_vc, *p_hidden;
    cudaGetSymbolAddress((void**)&p_h,      g_h);
    cudaGetSymbolAddress((void**)&p_qkv,    g_qkv);
    cudaGetSymbolAddress((void**)&p_attn,   g_attn);
    cudaGetSymbolAddress((void**)&p_x1,     g_x1);
    cudaGetSymbolAddress((void**)&p_x2,     g_x2);
    cudaGetSymbolAddress((void**)&p_ctx,    g_ctx);
    cudaGetSymbolAddress((void**)&p_qb,     g_qb);
    cudaGetSymbolAddress((void**)&p_kc,     g_kc);
    cudaGetSymbolAddress((void**)&p_vc,     g_vc);
    cudaGetSymbolAddress((void**)&p_hidden, g_hidden);

    // 1. adaLN modulation
    {
        dim3 grid(6 * DM / 256, BB);
        mod_kernel<<<grid, 256>>>(c, W_ada, b_ada);
    }

    // --- self-attention block ---
    lnmod_kernel<<<TTOK, 256>>>(x, 0 * DM, 1 * DM, p_h);
    launch_gemm<EPI_BIAS>(p_h, W_qkv, b_qkv, nullptr, p_qkv, TTOK, 3 * DM, DM);
    {
        dim3 grid(NSEQ / 64, NH, BB);
        self_attn_kernel<<<grid, 64>>>();
    }
    launch_gemm<EPI_BIAS_RES>(p_attn, W_proj, b_proj, x, p_x1, TTOK, DM, DM);

    // --- cross-attention block ---
    lnmod_kernel<<<TTOK, 256>>>(p_x1, 2 * DM, 3 * DM, p_h);
    launch_gemm<EPI_BIAS>(text, W_ctx, b_ctx, nullptr, p_ctx, TCTX, DM, TD);
    launch_gemm<EPI_NOBIAS>(p_h, W_q, nullptr, nullptr, p_qb, TTOK, DM, DM);
    launch_gemm<EPI_NOBIAS>(p_ctx, W_k, nullptr, nullptr, p_kc, TCTX, DM, DM);
    launch_gemm<EPI_NOBIAS>(p_ctx, W_v, nullptr, nullptr, p_vc, TCTX, DM, DM);
    {
        dim3 grid(NSEQ / 64, NH, BB);
        cross_attn_kernel<<<grid, 64>>>();
    }
    launch_gemm<EPI_BIAS_RES>(p_attn, W_out, b_out, p_x1, p_x2, TTOK, DM, DM);

    // --- MLP block ---
    lnmod_kernel<<<TTOK, 256>>>(p_x2, 4 * DM, 5 * DM, p_h);
    launch_gemm<EPI_BIAS_GELU>(p_h, W_fc1, b_fc1, nullptr, p_hidden, TTOK, 4 * DM, DM);
    launch_gemm<EPI_BIAS_RES>(p_hidden, W_fc2, b_fc2, p_x2, out, TTOK, DM, 4 * DM);
}

// round 4
// speedup vs baseline: 2.6247x; 1.3639x over previous
#include <cuda_runtime.h>
#include <math.h>
#include <stdint.h>

// ---------------------------------------------------------------------------
// Problem constants
// ---------------------------------------------------------------------------
#define BB 4
#define NSEQ 1024
#define DM 1024
#define NH 16
#define HD 64
#define TD 768
#define TL 77
#define TTOK (BB * NSEQ)   // 4096
#define TCTX (BB * TL)     // 308

// ---------------------------------------------------------------------------
// Scratch (static device globals; no allocation allowed)
// ---------------------------------------------------------------------------
__device__ float g_mod[BB * 6 * DM];
__device__ float g_h[TTOK * DM];
__device__ float g_qkv[TTOK * 3 * DM];
__device__ float g_attn[TTOK * DM];
__device__ float g_x1[TTOK * DM];
__device__ float g_x2[TTOK * DM];
__device__ float g_ctx[TCTX * DM];
__device__ float g_qb[TTOK * DM];
__device__ float g_kc[TCTX * DM];
__device__ float g_vc[TCTX * DM];
__device__ float g_hidden[TTOK * 4 * DM];

// ---------------------------------------------------------------------------
// Helpers
// ---------------------------------------------------------------------------
__device__ __forceinline__ float gelu_tanh(float x) {
    float x3 = x * x * x;
    float t  = tanhf(0.7978845608028654f * (x + 0.044715f * x3));
    return 0.5f * x * (1.0f + t);
}

__device__ __forceinline__ uint32_t f2tf32(float f) {
    uint32_t u;
    asm("cvt.rna.tf32.f32 %0, %1;" : "=r"(u) : "f"(f));
    return u;
}

__device__ __forceinline__ void mma1688(float* c, const uint32_t* a, const uint32_t* b) {
    asm volatile(
        "mma.sync.aligned.m16n8k8.row.col.f32.tf32.tf32.f32 "
        "{%0,%1,%2,%3}, {%4,%5,%6,%7}, {%8,%9}, {%0,%1,%2,%3};"
        : "+f"(c[0]), "+f"(c[1]), "+f"(c[2]), "+f"(c[3])
        : "r"(a[0]), "r"(a[1]), "r"(a[2]), "r"(a[3]), "r"(b[0]), "r"(b[1]));
}

// Epilogue modes
#define EPI_BIAS      0
#define EPI_BIAS_GELU 1
#define EPI_BIAS_RES  2
#define EPI_NOBIAS    3

// ---------------------------------------------------------------------------
// TF32 tensor-core GEMM: C[M,N] = A[M,K] @ W[K,N] (+bias)(+gelu)(+residual)
// BM=128, BN=128, BK=16, 256 threads (8 warps: 4 over M x 2 over N).
// ---------------------------------------------------------------------------
template <int EPI>
__global__ void __launch_bounds__(256) tgemm_kernel(
    const float* __restrict__ A, const float* __restrict__ W,
    const float* __restrict__ bias, const float* __restrict__ res,
    float* __restrict__ C, int M, int N, int K)
{
    __shared__ uint32_t As[128][20];
    __shared__ uint32_t Bs[16][136];

    const int tid  = threadIdx.x;
    const int lane = tid & 31;
    const int warp = tid >> 5;
    const int g = lane >> 2;
    const int t = lane & 3;
    const int wm = (warp & 3) * 32;
    const int wn = (warp >> 2) * 64;
    const int rowBase = blockIdx.y * 128;
    const int colBase = blockIdx.x * 128;

    const int arow = tid >> 2;
    const int acol = (tid & 3) * 4;
    const int wk   = tid >> 5;
    const int wn4  = (tid & 31) * 4;

    float acc[2][8][4];
#pragma unroll
    for (int mt = 0; mt < 2; mt++)
#pragma unroll
        for (int nt = 0; nt < 8; nt++)
#pragma unroll
            for (int i = 0; i < 4; i++) acc[mt][nt][i] = 0.0f;

    float4 aR0, aR1, wR0, wR1;

    {
        const int r0 = rowBase + arow, r1 = r0 + 64;
        aR0 = (r0 < M) ? *(const float4*)(A + (size_t)r0 * K + acol)
                       : make_float4(0.f, 0.f, 0.f, 0.f);
        aR1 = (r1 < M) ? *(const float4*)(A + (size_t)r1 * K + acol)
                       : make_float4(0.f, 0.f, 0.f, 0.f);
        wR0 = *(const float4*)(W + (size_t)wk       * N + colBase + wn4);
        wR1 = *(const float4*)(W + (size_t)(wk + 8) * N + colBase + wn4);
    }
    {
        As[arow][acol + 0] = f2tf32(aR0.x); As[arow][acol + 1] = f2tf32(aR0.y);
        As[arow][acol + 2] = f2tf32(aR0.z); As[arow][acol + 3] = f2tf32(aR0.w);
        As[arow + 64][acol + 0] = f2tf32(aR1.x); As[arow + 64][acol + 1] = f2tf32(aR1.y);
        As[arow + 64][acol + 2] = f2tf32(aR1.z); As[arow + 64][acol + 3] = f2tf32(aR1.w);
        uint4 b0 = make_uint4(f2tf32(wR0.x), f2tf32(wR0.y), f2tf32(wR0.z), f2tf32(wR0.w));
        uint4 b1 = make_uint4(f2tf32(wR1.x), f2tf32(wR1.y), f2tf32(wR1.z), f2tf32(wR1.w));
        *(uint4*)&Bs[wk][wn4]     = b0;
        *(uint4*)&Bs[wk + 8][wn4] = b1;
    }
    __syncthreads();

    for (int k0 = 0; k0 < K; k0 += 16) {
        const bool hasNext = (k0 + 16) < K;
        if (hasNext) {
            const int kn = k0 + 16;
            const int r0 = rowBase + arow, r1 = r0 + 64;
            aR0 = (r0 < M) ? *(const float4*)(A + (size_t)r0 * K + kn + acol)
                           : make_float4(0.f, 0.f, 0.f, 0.f);
            aR1 = (r1 < M) ? *(const float4*)(A + (size_t)r1 * K + kn + acol)
                           : make_float4(0.f, 0.f, 0.f, 0.f);
            wR0 = *(const float4*)(W + (size_t)(kn + wk)     * N + colBase + wn4);
            wR1 = *(const float4*)(W + (size_t)(kn + wk + 8) * N + colBase + wn4);
        }

#pragma unroll
        for (int ks = 0; ks < 16; ks += 8) {
            uint32_t af[2][4];
            uint32_t bf[8][2];
#pragma unroll
            for (int mt = 0; mt < 2; mt++) {
                const int m = wm + mt * 16;
                af[mt][0] = As[m + g][ks + t];
                af[mt][1] = As[m + g + 8][ks + t];
                af[mt][2] = As[m + g][ks + t + 4];
                af[mt][3] = As[m + g + 8][ks + t + 4];
            }
#pragma unroll
            for (int nt = 0; nt < 8; nt++) {
                const int n = wn + nt * 8;
                bf[nt][0] = Bs[ks + t][n + g];
                bf[nt][1] = Bs[ks + t + 4][n + g];
            }
#pragma unroll
            for (int mt = 0; mt < 2; mt++)
#pragma unroll
                for (int nt = 0; nt < 8; nt++)
                    mma1688(acc[mt][nt], af[mt], bf[nt]);
        }
        __syncthreads();

        if (hasNext) {
            As[arow][acol + 0] = f2tf32(aR0.x); As[arow][acol + 1] = f2tf32(aR0.y);
            As[arow][acol + 2] = f2tf32(aR0.z); As[arow][acol + 3] = f2tf32(aR0.w);
            As[arow + 64][acol + 0] = f2tf32(aR1.x); As[arow + 64][acol + 1] = f2tf32(aR1.y);
            As[arow + 64][acol + 2] = f2tf32(aR1.z); As[arow + 64][acol + 3] = f2tf32(aR1.w);
            uint4 b0 = make_uint4(f2tf32(wR0.x), f2tf32(wR0.y), f2tf32(wR0.z), f2tf32(wR0.w));
            uint4 b1 = make_uint4(f2tf32(wR1.x), f2tf32(wR1.y), f2tf32(wR1.z), f2tf32(wR1.w));
            *(uint4*)&Bs[wk][wn4]     = b0;
            *(uint4*)&Bs[wk + 8][wn4] = b1;
            __syncthreads();
        }
    }

#pragma unroll
    for (int mt = 0; mt < 2; mt++) {
        const int row0 = rowBase + wm + mt * 16 + g;
        const int row1 = row0 + 8;
#pragma unroll
        for (int nt = 0; nt < 8; nt++) {
            const int col = colBase + wn + nt * 8 + t * 2;
            float b0 = 0.f, b1 = 0.f;
            if (EPI != EPI_NOBIAS) { b0 = bias[col]; b1 = bias[col + 1]; }
            float v0 = acc[mt][nt][0] + b0;
            float v1 = acc[mt][nt][1] + b1;
            float v2 = acc[mt][nt][2] + b0;
            float v3 = acc[mt][nt][3] + b1;
            if (EPI == EPI_BIAS_GELU) {
                v0 = gelu_tanh(v0); v1 = gelu_tanh(v1);
                v2 = gelu_tanh(v2); v3 = gelu_tanh(v3);
            }
            if (row0 < M) {
                if (EPI == EPI_BIAS_RES) {
                    float2 r = *(const float2*)(res + (size_t)row0 * N + col);
                    v0 += r.x; v1 += r.y;
                }
                *(float2*)(C + (size_t)row0 * N + col) = make_float2(v0, v1);
            }
            if (row1 < M) {
                if (EPI == EPI_BIAS_RES) {
                    float2 r = *(const float2*)(res + (size_t)row1 * N + col);
                    v2 += r.x; v3 += r.y;
                }
                *(float2*)(C + (size_t)row1 * N + col) = make_float2(v2, v3);
            }
        }
    }
}

// ---------------------------------------------------------------------------
// adaLN modulation
// ---------------------------------------------------------------------------
__global__ void __launch_bounds__(256) mod_kernel(
    const float* __restrict__ c, const float* __restrict__ W,
    const float* __restrict__ bias)
{
    const int b = blockIdx.y;
    const int col = blockIdx.x * 256 + threadIdx.x;
    __shared__ float sc[DM];
    for (int i = threadIdx.x; i < DM; i += 256) {
        float v = c[b * DM + i];
        sc[i] = v / (1.0f + __expf(-v));
    }
    __syncthreads();
    float acc = 0.0f;
#pragma unroll 8
    for (int k = 0; k < DM; k++)
        acc = fmaf(sc[k], W[(size_t)k * (6 * DM) + col], acc);
    g_mod[b * 6 * DM + col] = acc + bias[col];
}

// ---------------------------------------------------------------------------
// LayerNorm + modulate
// ---------------------------------------------------------------------------
__global__ void __launch_bounds__(256) lnmod_kernel(
    const float* __restrict__ x, int shOff, int scOff, float* __restrict__ out)
{
    const int row = blockIdx.x;
    const int b = row >> 10;
    const int tid = threadIdx.x;

    float4 v = ((const float4*)(x + (size_t)row * DM))[tid];
    float s  = v.x + v.y + v.z + v.w;
    float s2 = v.x * v.x + v.y * v.y + v.z * v.z + v.w * v.w;

    __shared__ float red[16];
#pragma unroll
    for (int off = 16; off > 0; off >>= 1) {
        s  += __shfl_xor_sync(0xffffffffu, s,  off);
        s2 += __shfl_xor_sync(0xffffffffu, s2, off);
    }
    const int warp = tid >> 5, lane = tid & 31;
    if (lane == 0) { red[warp] = s; red[warp + 8] = s2; }
    __syncthreads();
    if (tid == 0) {
        float ts = 0.f, ts2 = 0.f;
#pragma unroll
        for (int i = 0; i < 8; i++) { ts += red[i]; ts2 += red[i + 8]; }
        float mu  = ts * (1.0f / DM);
        float var = ts2 * (1.0f / DM) - mu * mu;
        red[0] = mu;
        red[1] = rsqrtf(var + 1e-6f);
    }
    __syncthreads();
    const float mu = red[0], rs = red[1];

    const float* modp = g_mod + b * 6 * DM;
    const int cc = tid * 4;
    float4 sh  = *(const float4*)(modp + shOff + cc);
    float4 scv = *(const float4*)(modp + scOff + cc);
    float4 o;
    o.x = (v.x - mu) * rs * (1.0f + scv.x) + sh.x;
    o.y = (v.y - mu) * rs * (1.0f + scv.y) + sh.y;
    o.z = (v.z - mu) * rs * (1.0f + scv.z) + sh.z;
    o.w = (v.w - mu) * rs * (1.0f + scv.w) + sh.w;
    ((float4*)(out + (size_t)row * DM))[tid] = o;
}

// ---------------------------------------------------------------------------
// Tensor-core flash self-attention.
// grid (16, 16, 4) = (qtile, head, batch); 128 threads = 4 warps.
// Warp w owns 16 query rows (w*16 .. w*16+15) of the 64-query tile.
// K/V tiles (64x64) staged in smem as tf32 bits, [64][68] padding ->
// conflict-free fragment reads (bank = (4g+t)%32, all distinct).
// P is written back into the K buffer (K dead after QK^T) -> 34.8KB smem.
// ---------------------------------------------------------------------------
#define AT_PAD 68

__global__ void __launch_bounds__(128) flash_attn_kernel()
{
    __shared__ uint32_t Ks[64][AT_PAD];   // K tile, then P tile
    __shared__ uint32_t Vs[64][AT_PAD];

    const int qt = blockIdx.x, h = blockIdx.y, b = blockIdx.z;
    const int tid  = threadIdx.x;
    const int lane = tid & 31;
    const int warp = tid >> 5;
    const int g = lane >> 2;
    const int t = lane & 3;
    const int rw = warp * 16;
    const int qbase = b * NSEQ + qt * 64;

    // Q A-fragments (16 rows per warp, 64 d = 8 k-slices), scaled by 1/8
    uint32_t qa[8][4];
    {
        const float* q0 = g_qkv + (size_t)(qbase + rw + g)     * (3 * DM) + h * 64;
        const float* q1 = g_qkv + (size_t)(qbase + rw + g + 8) * (3 * DM) + h * 64;
#pragma unroll
        for (int ks = 0; ks < 8; ks++) {
            qa[ks][0] = f2tf32(q0[ks * 8 + t]     * 0.125f);
            qa[ks][1] = f2tf32(q1[ks * 8 + t]     * 0.125f);
            qa[ks][2] = f2tf32(q0[ks * 8 + t + 4] * 0.125f);
            qa[ks][3] = f2tf32(q1[ks * 8 + t + 4] * 0.125f);
        }
    }

    float o[8][4];
#pragma unroll
    for (int nt = 0; nt < 8; nt++)
#pragma unroll
        for (int i = 0; i < 4; i++) o[nt][i] = 0.0f;
    float m0 = -1e30f, m1 = -1e30f, l0 = 0.0f, l1 = 0.0f;

    // gmem->smem tile load mapping: thread -> (row, half-row of 8 float4)
    const int rk = tid >> 1;
    const int f4 = (tid & 1) * 8;

    for (int kt = 0; kt < 16; kt++) {
        __syncthreads();   // prior PV reads of Ks/Vs complete
        {
            const size_t krow = (size_t)(b * NSEQ + kt * 64 + rk) * (3 * DM);
            const float4* kp = (const float4*)(g_qkv + krow + DM     + h * 64) + f4;
            const float4* vp = (const float4*)(g_qkv + krow + 2 * DM + h * 64) + f4;
            uint4* kd = (uint4*)&Ks[rk][f4 * 4];
            uint4* vd = (uint4*)&Vs[rk][f4 * 4];
#pragma unroll
            for (int i = 0; i < 8; i++) {
                float4 kv = kp[i];
                float4 vv = vp[i];
                kd[i] = make_uint4(f2tf32(kv.x), f2tf32(kv.y), f2tf32(kv.z), f2tf32(kv.w));
                vd[i] = make_uint4(f2tf32(vv.x), f2tf32(vv.y), f2tf32(vv.z), f2tf32(vv.w));
            }
        }
        __syncthreads();   // tiles ready

        // S = Q @ K^T  (per warp: 16 x 64)
        float s[8][4];
#pragma unroll
        for (int nt = 0; nt < 8; nt++)
#pragma unroll
            for (int i = 0; i < 4; i++) s[nt][i] = 0.0f;
#pragma unroll
        for (int ks = 0; ks < 8; ks++) {
#pragma unroll
            for (int nt = 0; nt < 8; nt++) {
                uint32_t bf[2];
                bf[0] = Ks[nt * 8 + g][ks * 8 + t];
                bf[1] = Ks[nt * 8 + g][ks * 8 + t + 4];
                mma1688(s[nt], qa[ks], bf);
            }
        }

        // Online softmax in fragments. Rows: g (c0,c1) and g+8 (c2,c3).
        float tmax0 = -1e30f, tmax1 = -1e30f;
#pragma unroll
        for (int nt = 0; nt < 8; nt++) {
            tmax0 = fmaxf(tmax0, fmaxf(s[nt][0], s[nt][1]));
            tmax1 = fmaxf(tmax1, fmaxf(s[nt][2], s[nt][3]));
        }
        tmax0 = fmaxf(tmax0, __shfl_xor_sync(0xffffffffu, tmax0, 1));
        tmax0 = fmaxf(tmax0, __shfl_xor_sync(0xffffffffu, tmax0, 2));
        tmax1 = fmaxf(tmax1, __shfl_xor_sync(0xffffffffu, tmax1, 1));
        tmax1 = fmaxf(tmax1, __shfl_xor_sync(0xffffffffu, tmax1, 2));

        const float mn0 = fmaxf(m0, tmax0);
        const float mn1 = fmaxf(m1, tmax1);
        const float corr0 = __expf(m0 - mn0);
        const float corr1 = __expf(m1 - mn1);

        float sum0 = 0.0f, sum1 = 0.0f;
#pragma unroll
        for (int nt = 0; nt < 8; nt++) {
            s[nt][0] = __expf(s[nt][0] - mn0); sum0 += s[nt][0];
            s[nt][1] = __expf(s[nt][1] - mn0); sum0 += s[nt][1];
            s[nt][2] = __expf(s[nt][2] - mn1); sum1 += s[nt][2];
            s[nt][3] = __expf(s[nt][3] - mn1); sum1 += s[nt][3];
        }
        sum0 += __shfl_xor_sync(0xffffffffu, sum0, 1);
        sum0 += __shfl_xor_sync(0xffffffffu, sum0, 2);
        sum1 += __shfl_xor_sync(0xffffffffu, sum1, 1);
        sum1 += __shfl_xor_sync(0xffffffffu, sum1, 2);

        l0 = l0 * corr0 + sum0;
        l1 = l1 * corr1 + sum1;
        m0 = mn0; m1 = mn1;
#pragma unroll
        for (int nt = 0; nt < 8; nt++) {
            o[nt][0] *= corr0; o[nt][1] *= corr0;
            o[nt][2] *= corr1; o[nt][3] *= corr1;
        }

        // Write P into Ks (K no longer needed)
        __syncthreads();   // all warps finished reading K
#pragma unroll
        for (int nt = 0; nt < 8; nt++) {
            *(uint2*)&Ks[rw + g][nt * 8 + 2 * t] =
                make_uint2(f2tf32(s[nt][0]), f2tf32(s[nt][1]));
            *(uint2*)&Ks[rw + 8 + g][nt * 8 + 2 * t] =
                make_uint2(f2tf32(s[nt][2]), f2tf32(s[nt][3]));
        }
        __syncthreads();   // P ready

        // O += P @ V  (k = keys, n = d)
#pragma unroll
        for (int ks = 0; ks < 8; ks++) {
            uint32_t a[4];
            a[0] = Ks[rw + g][ks * 8 + t];
            a[1] = Ks[rw + 8 + g][ks * 8 + t];
            a[2] = Ks[rw + g][ks * 8 + t + 4];
            a[3] = Ks[rw + 8 + g][ks * 8 + t + 4];
#pragma unroll
            for (int nt = 0; nt < 8; nt++) {
                uint32_t bf[2];
                bf[0] = Vs[ks * 8 + t][nt * 8 + g];
                bf[1] = Vs[ks * 8 + t + 4][nt * 8 + g];
                mma1688(o[nt], a, bf);
            }
        }
    }

    // Epilogue: normalize and store
    const float inv0 = 1.0f / l0;
    const float inv1 = 1.0f / l1;
    float* op0 = g_attn + (size_t)(qbase + rw + g)     * DM + h * 64;
    float* op1 = g_attn + (size_t)(qbase + rw + g + 8) * DM + h * 64;
#pragma unroll
    for (int nt = 0; nt < 8; nt++) {
        *(float2*)(op0 + nt * 8 + 2 * t) = make_float2(o[nt][0] * inv0, o[nt][1] * inv0);
        *(float2*)(op1 + nt * 8 + 2 * t) = make_float2(o[nt][2] * inv1, o[nt][3] * inv1);
    }
}

// ---------------------------------------------------------------------------
// Cross-attention: 77 keys. Two-pass softmax. Row-major K/V tiles + float4.
// ---------------------------------------------------------------------------
__global__ void __launch_bounds__(64) cross_attn_kernel()
{
    __shared__ float Kc[TL][64];
    __shared__ float Vc[TL][64];

    const int qt = blockIdx.x, h = blockIdx.y, b = blockIdx.z;
    const int tid = threadIdx.x;

    for (int i = tid; i < TL * 16; i += 64) {
        const int l = i >> 4;
        const int c4 = (i & 15);
        const size_t src = (size_t)(b * TL + l) * DM + h * 64 + c4 * 4;
        ((float4*)Kc[l])[c4] = *(const float4*)(g_kc + src);
        ((float4*)Vc[l])[c4] = *(const float4*)(g_vc + src);
    }
    __syncthreads();

    const int row = b * NSEQ + qt * 64 + tid;
    float q[64];
    {
        const float4* qp = (const float4*)(g_qb + (size_t)row * DM + h * 64);
#pragma unroll
        for (int i = 0; i < 16; i++) {
            float4 tq = qp[i];
            q[4 * i + 0] = tq.x * 0.125f;
            q[4 * i + 1] = tq.y * 0.125f;
            q[4 * i + 2] = tq.z * 0.125f;
            q[4 * i + 3] = tq.w * 0.125f;
        }
    }

    float m = -1e30f;
    for (int l = 0; l < TL; l++) {
        const float4* kr = (const float4*)Kc[l];
        float s0 = 0.f, s1 = 0.f, s2 = 0.f, s3 = 0.f;
#pragma unroll
        for (int i = 0; i < 16; i++) {
            float4 kv = kr[i];
            s0 = fmaf(q[4 * i + 0], kv.x, s0);
            s1 = fmaf(q[4 * i + 1], kv.y, s1);
            s2 = fmaf(q[4 * i + 2], kv.z, s2);
            s3 = fmaf(q[4 * i + 3], kv.w, s3);
        }
        m = fmaxf(m, (s0 + s1) + (s2 + s3));
    }

    float o[64];
#pragma unroll
    for (int d = 0; d < 64; d++) o[d] = 0.0f;
    float lsum = 0.0f;
    for (int l = 0; l < TL; l++) {
        const float4* kr = (const float4*)Kc[l];
        float s0 = 0.f, s1 = 0.f, s2 = 0.f, s3 = 0.f;
#pragma unroll
        for (int i = 0; i < 16; i++) {
            float4 kv = kr[i];
            s0 = fmaf(q[4 * i + 0], kv.x, s0);
            s1 = fmaf(q[4 * i + 1], kv.y, s1);
            s2 = fmaf(q[4 * i + 2], kv.z, s2);
            s3 = fmaf(q[4 * i + 3], kv.w, s3);
        }
        const float p = __expf((s0 + s1) + (s2 + s3) - m);
        lsum += p;
        const float4* vr = (const float4*)Vc[l];
#pragma unroll
        for (int i = 0; i < 16; i++) {
            float4 vv = vr[i];
            o[4 * i + 0] = fmaf(p, vv.x, o[4 * i + 0]);
            o[4 * i + 1] = fmaf(p, vv.y, o[4 * i + 1]);
            o[4 * i + 2] = fmaf(p, vv.z, o[4 * i + 2]);
            o[4 * i + 3] = fmaf(p, vv.w, o[4 * i + 3]);
        }
    }

    const float inv = 1.0f / lsum;
    float4* op = (float4*)(g_attn + (size_t)row * DM + h * 64);
#pragma unroll
    for (int i = 0; i < 16; i++)
        op[i] = make_float4(o[4 * i + 0] * inv, o[4 * i + 1] * inv,
                            o[4 * i + 2] * inv, o[4 * i + 3] * inv);
}

// ---------------------------------------------------------------------------
// Host side
// ---------------------------------------------------------------------------
template <int EPI>
static void launch_gemm(const float* A, const float* W, const float* bias,
                        const float* res, float* C, int M, int N, int K)
{
    dim3 grid(N / 128, (M + 127) / 128);
    tgemm_kernel<EPI><<<grid, 256>>>(A, W, bias, res, C, M, N, K);
}

extern "C" void kernel_launch(void* const* d_in, const int* in_sizes, int n_in,
                              void* d_out, int out_size)
{
    const float* x       = (const float*)d_in[0];
    const float* c       = (const float*)d_in[1];
    const float* text    = (const float*)d_in[2];
    const float* W_ada   = (const float*)d_in[3];
    const float* b_ada   = (const float*)d_in[4];
    const float* W_qkv   = (const float*)d_in[5];
    const float* b_qkv   = (const float*)d_in[6];
    const float* W_proj  = (const float*)d_in[7];
    const float* b_proj  = (const float*)d_in[8];
    const float* W_ctx   = (const float*)d_in[9];
    const float* b_ctx   = (const float*)d_in[10];
    const float* W_q     = (const float*)d_in[11];
    const float* W_k     = (const float*)d_in[12];
    const float* W_v     = (const float*)d_in[13];
    const float* W_out   = (const float*)d_in[14];
    const float* b_out   = (const float*)d_in[15];
    const float* W_fc1   = (const float*)d_in[16];
    const float* b_fc1   = (const float*)d_in[17];
    const float* W_fc2   = (const float*)d_in[18];
    const float* b_fc2   = (const float*)d_in[19];
    float* out = (float*)d_out;

    float *p_h, *p_qkv, *p_attn, *p_x1, *p_x2, *p_ctx, *p_qb, *p_kc, *p_vc, *p_hidden;
    cudaGetSymbolAddress((void**)&p_h,      g_h);
    cudaGetSymbolAddress((void**)&p_qkv,    g_qkv);
    cudaGetSymbolAddress((void**)&p_attn,   g_attn);
    cudaGetSymbolAddress((void**)&p_x1,     g_x1);
    cudaGetSymbolAddress((void**)&p_x2,     g_x2);
    cudaGetSymbolAddress((void**)&p_ctx,    g_ctx);
    cudaGetSymbolAddress((void**)&p_qb,     g_qb);
    cudaGetSymbolAddress((void**)&p_kc,     g_kc);
    cudaGetSymbolAddress((void**)&p_vc,     g_vc);
    cudaGetSymbolAddress((void**)&p_hidden, g_hidden);

    // 1. adaLN modulation
    {
        dim3 grid(6 * DM / 256, BB);
        mod_kernel<<<grid, 256>>>(c, W_ada, b_ada);
    }

    // --- self-attention block ---
    lnmod_kernel<<<TTOK, 256>>>(x, 0 * DM, 1 * DM, p_h);
    launch_gemm<EPI_BIAS>(p_h, W_qkv, b_qkv, nullptr, p_qkv, TTOK, 3 * DM, DM);
    {
        dim3 grid(NSEQ / 64, NH, BB);
        flash_attn_kernel<<<grid, 128>>>();
    }
    launch_gemm<EPI_BIAS_RES>(p_attn, W_proj, b_proj, x, p_x1, TTOK, DM, DM);

    // --- cross-attention block ---
    lnmod_kernel<<<TTOK, 256>>>(p_x1, 2 * DM, 3 * DM, p_h);
    launch_gemm<EPI_BIAS>(text, W_ctx, b_ctx, nullptr, p_ctx, TCTX, DM, TD);
    launch_gemm<EPI_NOBIAS>(p_h, W_q, nullptr, nullptr, p_qb, TTOK, DM, DM);
    launch_gemm<EPI_NOBIAS>(p_ctx, W_k, nullptr, nullptr, p_kc, TCTX, DM, DM);
    launch_gemm<EPI_NOBIAS>(p_ctx, W_v, nullptr, nullptr, p_vc, TCTX, DM, DM);
    {
        dim3 grid(NSEQ / 64, NH, BB);
        cross_attn_kernel<<<grid, 64>>>();
    }
    launch_gemm<EPI_BIAS_RES>(p_attn, W_out, b_out, p_x1, p_x2, TTOK, DM, DM);

    // --- MLP block ---
    lnmod_kernel<<<TTOK, 256>>>(p_x2, 4 * DM, 5 * DM, p_h);
    launch_gemm<EPI_BIAS_GELU>(p_h, W_fc1, b_fc1, nullptr, p_hidden, TTOK, 4 * DM, DM);
    launch_gemm<EPI_BIAS_RES>(p_hidden, W_fc2, b_fc2, p_x2, out, TTOK, DM, 4 * DM);
}

// round 7
// speedup vs baseline: 2.9015x; 1.1055x over previous
#include <cuda_runtime.h>
#include <math.h>
#include <stdint.h>

// ---------------------------------------------------------------------------
// Problem constants
// ---------------------------------------------------------------------------
#define BB 4
#define NSEQ 1024
#define DM 1024
#define NH 16
#define HD 64
#define TD 768
#define TL 77
#define TTOK (BB * NSEQ)   // 4096
#define TCTX (BB * TL)     // 308

// ---------------------------------------------------------------------------
// Scratch (static device globals; no allocation allowed)
// ---------------------------------------------------------------------------
__device__ float g_mod[BB * 6 * DM];
__device__ float g_h[TTOK * DM];
__device__ float g_qkv[TTOK * 3 * DM];
__device__ float g_attn[TTOK * DM];
__device__ float g_x1[TTOK * DM];
__device__ float g_x2[TTOK * DM];
__device__ float g_ctx[TCTX * DM];
__device__ float g_qb[TTOK * DM];
__device__ float g_kc[TCTX * DM];
__device__ float g_vc[TCTX * DM];
__device__ float g_hidden[TTOK * 4 * DM];

// ---------------------------------------------------------------------------
// Helpers
// ---------------------------------------------------------------------------
__device__ __forceinline__ float gelu_tanh(float x) {
    float x3 = x * x * x;
    float t  = tanhf(0.7978845608028654f * (x + 0.044715f * x3));
    return 0.5f * x * (1.0f + t);
}

__device__ __forceinline__ uint32_t f2tf32(float f) {
    uint32_t u;
    asm("cvt.rna.tf32.f32 %0, %1;" : "=r"(u) : "f"(f));
    return u;
}

__device__ __forceinline__ uint4 rna4(float4 v) {
    return make_uint4(f2tf32(v.x), f2tf32(v.y), f2tf32(v.z), f2tf32(v.w));
}

__device__ __forceinline__ void mma1688(float* c, const uint32_t* a, const uint32_t* b) {
    asm volatile(
        "mma.sync.aligned.m16n8k8.row.col.f32.tf32.tf32.f32 "
        "{%0,%1,%2,%3}, {%4,%5,%6,%7}, {%8,%9}, {%0,%1,%2,%3};"
        : "+f"(c[0]), "+f"(c[1]), "+f"(c[2]), "+f"(c[3])
        : "r"(a[0]), "r"(a[1]), "r"(a[2]), "r"(a[3]), "r"(b[0]), "r"(b[1]));
}

__device__ __forceinline__ void ldsm4(uint32_t* r, uint32_t saddr) {
    asm volatile(
        "ldmatrix.sync.aligned.m8n8.x4.shared.b16 {%0,%1,%2,%3}, [%4];"
        : "=r"(r[0]), "=r"(r[1]), "=r"(r[2]), "=r"(r[3]) : "r"(saddr));
}

// Epilogue modes
#define EPI_BIAS      0
#define EPI_BIAS_GELU 1
#define EPI_BIAS_RES  2
#define EPI_NOBIAS    3

// ---------------------------------------------------------------------------
// TF32 tensor-core GEMM v2: C[M,N] = A[M,K] @ W[K,N] (+bias)(+gelu)(+res)
// BM=BN=128, BK=16, 128 threads = 4 warps, warp tile 64x64.
// Double-buffered smem. A fragments via ldmatrix.x4 (pitch 20, conflict-free),
// B fragments via scalar LDS from [k][n] (pitch 136, conflict-free).
// ---------------------------------------------------------------------------
#define AS_PITCH 20
#define BS_PITCH 136
#define AS_BUFB (128 * AS_PITCH * 4)   // bytes per A buffer

template <int EPI>
__global__ void __launch_bounds__(128) tgemm_kernel(
    const float* __restrict__ A, const float* __restrict__ W,
    const float* __restrict__ bias, const float* __restrict__ res,
    float* __restrict__ C, int M, int N, int K)
{
    __shared__ uint32_t As[2][128][AS_PITCH];
    __shared__ uint32_t Bs[2][16][BS_PITCH];

    const int tid  = threadIdx.x;
    const int lane = tid & 31;
    const int warp = tid >> 5;
    const int g = lane >> 2;
    const int t = lane & 3;
    const int wm = (warp & 1) * 64;
    const int wn = (warp >> 1) * 64;
    const int rowBase = blockIdx.y * 128;
    const int colBase = blockIdx.x * 128;

    const int j8  = lane & 7;
    const int mtx = lane >> 3;
    const uint32_t asBase = (uint32_t)__cvta_generic_to_shared(&As[0][0][0]);
    uint32_t aAddr[4];
#pragma unroll
    for (int mt = 0; mt < 4; mt++)
        aAddr[mt] = asBase +
            ((wm + mt * 16 + (mtx & 1) * 8 + j8) * AS_PITCH + (mtx >> 1) * 4) * 4;

    float acc[4][8][4];
#pragma unroll
    for (int mt = 0; mt < 4; mt++)
#pragma unroll
        for (int nt = 0; nt < 8; nt++)
#pragma unroll
            for (int i = 0; i < 4; i++) acc[mt][nt][i] = 0.0f;

    float4 aPre[4], bPre[4];

    // prologue: load k-slice 0
#pragma unroll
    for (int i = 0; i < 4; i++) {
        const int f4 = tid + i * 128;
        const int ar = f4 >> 2, ac = (f4 & 3) * 4;
        const int row = rowBase + ar;
        aPre[i] = (row < M) ? *(const float4*)(A + (size_t)row * K + ac)
                            : make_float4(0.f, 0.f, 0.f, 0.f);
        const int bk = f4 >> 5, bn = (f4 & 31) * 4;
        bPre[i] = *(const float4*)(W + (size_t)bk * N + colBase + bn);
    }
#pragma unroll
    for (int i = 0; i < 4; i++) {
        const int f4 = tid + i * 128;
        const int ar = f4 >> 2, ac = (f4 & 3) * 4;
        *(uint4*)&As[0][ar][ac] = rna4(aPre[i]);
        const int bk = f4 >> 5, bn = (f4 & 31) * 4;
        *(uint4*)&Bs[0][bk][bn] = rna4(bPre[i]);
    }
    __syncthreads();

    int buf = 0;
    for (int k0 = 0; k0 < K; k0 += 16) {
        const bool hasNext = (k0 + 16) < K;
        if (hasNext) {
            const int kn = k0 + 16;
#pragma unroll
            for (int i = 0; i < 4; i++) {
                const int f4 = tid + i * 128;
                const int ar = f4 >> 2, ac = (f4 & 3) * 4;
                const int row = rowBase + ar;
                aPre[i] = (row < M) ? *(const float4*)(A + (size_t)row * K + kn + ac)
                                    : make_float4(0.f, 0.f, 0.f, 0.f);
                const int bk = f4 >> 5, bn = (f4 & 31) * 4;
                bPre[i] = *(const float4*)(W + (size_t)(kn + bk) * N + colBase + bn);
            }
        }

        const uint32_t aOff = (uint32_t)buf * AS_BUFB;
        const uint32_t* __restrict__ bsBuf = &Bs[buf][0][0];
#pragma unroll
        for (int ks = 0; ks < 16; ks += 8) {
            uint32_t af[4][4];
#pragma unroll
            for (int mt = 0; mt < 4; mt++)
                ldsm4(af[mt], aAddr[mt] + aOff + ks * 4);
            uint32_t bf[8][2];
#pragma unroll
            for (int nt = 0; nt < 8; nt++) {
                bf[nt][0] = bsBuf[(ks + t)     * BS_PITCH + wn + nt * 8 + g];
                bf[nt][1] = bsBuf[(ks + t + 4) * BS_PITCH + wn + nt * 8 + g];
            }
#pragma unroll
            for (int mt = 0; mt < 4; mt++)
#pragma unroll
                for (int nt = 0; nt < 8; nt++)
                    mma1688(acc[mt][nt], af[mt], bf[nt]);
        }

        if (hasNext) {
            const int nb = buf ^ 1;
#pragma unroll
            for (int i = 0; i < 4; i++) {
                const int f4 = tid + i * 128;
                const int ar = f4 >> 2, ac = (f4 & 3) * 4;
                *(uint4*)&As[nb][ar][ac] = rna4(aPre[i]);
                const int bk = f4 >> 5, bn = (f4 & 31) * 4;
                *(uint4*)&Bs[nb][bk][bn] = rna4(bPre[i]);
            }
            __syncthreads();
            buf = nb;
        }
    }

    // Epilogue
#pragma unroll
    for (int mt = 0; mt < 4; mt++) {
        const int row0 = rowBase + wm + mt * 16 + g;
        const int row1 = row0 + 8;
#pragma unroll
        for (int nt = 0; nt < 8; nt++) {
            const int col = colBase + wn + nt * 8 + t * 2;
            float b0 = 0.f, b1 = 0.f;
            if (EPI != EPI_NOBIAS) { b0 = bias[col]; b1 = bias[col + 1]; }
            float v0 = acc[mt][nt][0] + b0;
            float v1 = acc[mt][nt][1] + b1;
            float v2 = acc[mt][nt][2] + b0;
            float v3 = acc[mt][nt][3] + b1;
            if (EPI == EPI_BIAS_GELU) {
                v0 = gelu_tanh(v0); v1 = gelu_tanh(v1);
                v2 = gelu_tanh(v2); v3 = gelu_tanh(v3);
            }
            if (row0 < M) {
                if (EPI == EPI_BIAS_RES) {
                    float2 r = *(const float2*)(res + (size_t)row0 * N + col);
                    v0 += r.x; v1 += r.y;
                }
                *(float2*)(C + (size_t)row0 * N + col) = make_float2(v0, v1);
            }
            if (row1 < M) {
                if (EPI == EPI_BIAS_RES) {
                    float2 r = *(const float2*)(res + (size_t)row1 * N + col);
                    v2 += r.x; v3 += r.y;
                }
                *(float2*)(C + (size_t)row1 * N + col) = make_float2(v2, v3);
            }
        }
    }
}

// ---------------------------------------------------------------------------
// adaLN modulation
// ---------------------------------------------------------------------------
__global__ void __launch_bounds__(256) mod_kernel(
    const float* __restrict__ c, const float* __restrict__ W,
    const float* __restrict__ bias)
{
    const int b = blockIdx.y;
    const int col = blockIdx.x * 256 + threadIdx.x;
    __shared__ float sc[DM];
    for (int i = threadIdx.x; i < DM; i += 256) {
        float v = c[b * DM + i];
        sc[i] = v / (1.0f + __expf(-v));
    }
    __syncthreads();
    float acc = 0.0f;
#pragma unroll 8
    for (int k = 0; k < DM; k++)
        acc = fmaf(sc[k], W[(size_t)k * (6 * DM) + col], acc);
    g_mod[b * 6 * DM + col] = acc + bias[col];
}

// ---------------------------------------------------------------------------
// LayerNorm + modulate
// ---------------------------------------------------------------------------
__global__ void __launch_bounds__(256) lnmod_kernel(
    const float* __restrict__ x, int shOff, int scOff, float* __restrict__ out)
{
    const int row = blockIdx.x;
    const int b = row >> 10;
    const int tid = threadIdx.x;

    float4 v = ((const float4*)(x + (size_t)row * DM))[tid];
    float s  = v.x + v.y + v.z + v.w;
    float s2 = v.x * v.x + v.y * v.y + v.z * v.z + v.w * v.w;

    __shared__ float red[16];
#pragma unroll
    for (int off = 16; off > 0; off >>= 1) {
        s  += __shfl_xor_sync(0xffffffffu, s,  off);
        s2 += __shfl_xor_sync(0xffffffffu, s2, off);
    }
    const int warp = tid >> 5, lane = tid & 31;
    if (lane == 0) { red[warp] = s; red[warp + 8] = s2; }
    __syncthreads();
    if (tid == 0) {
        float ts = 0.f, ts2 = 0.f;
#pragma unroll
        for (int i = 0; i < 8; i++) { ts += red[i]; ts2 += red[i + 8]; }
        float mu  = ts * (1.0f / DM);
        float var = ts2 * (1.0f / DM) - mu * mu;
        red[0] = mu;
        red[1] = rsqrtf(var + 1e-6f);
    }
    __syncthreads();
    const float mu = red[0], rs = red[1];

    const float* modp = g_mod + b * 6 * DM;
    const int cc = tid * 4;
    float4 sh  = *(const float4*)(modp + shOff + cc);
    float4 scv = *(const float4*)(modp + scOff + cc);
    float4 o;
    o.x = (v.x - mu) * rs * (1.0f + scv.x) + sh.x;
    o.y = (v.y - mu) * rs * (1.0f + scv.y) + sh.y;
    o.z = (v.z - mu) * rs * (1.0f + scv.z) + sh.z;
    o.w = (v.w - mu) * rs * (1.0f + scv.w) + sh.w;
    ((float4*)(out + (size_t)row * DM))[tid] = o;
}

// ---------------------------------------------------------------------------
// Tensor-core flash self-attention v2.
// grid (8, 16, 4) = (qtile of 128, head, batch); 128 threads = 4 warps.
// Warp owns 32 query rows (2 m16 tiles). Keys processed in 32-wide chunks.
// K tile [key][d] pitch 76 (ldmatrix-friendly, conflict-free);
// V tile [key][d] pitch 88 (scalar-LDS conflict-free for PV B-frags).
// P stays in registers: S accumulator frags -> A frags via warp shuffles.
// ---------------------------------------------------------------------------
#define KS_PITCH 76
#define VS_PITCH 88

__global__ void __launch_bounds__(128) flash_attn_kernel()
{
    __shared__ uint32_t Ks[64][KS_PITCH];
    __shared__ uint32_t Vs[64][VS_PITCH];

    const int qt = blockIdx.x, h = blockIdx.y, b = blockIdx.z;
    const int tid  = threadIdx.x;
    const int lane = tid & 31;
    const int warp = tid >> 5;
    const int g = lane >> 2;
    const int t = lane & 3;
    const int rw = warp * 32;
    const int qbase = b * NSEQ + qt * 128;

    // Q fragments: 2 m-tiles x 8 k-slices, scaled by 1/8
    uint32_t qa[8][2][4];
#pragma unroll
    for (int mt = 0; mt < 2; mt++) {
        const float* q0 = g_qkv + (size_t)(qbase + rw + mt * 16 + g) * (3 * DM) + h * 64;
        const float* q1 = q0 + (size_t)8 * (3 * DM);
#pragma unroll
        for (int ks = 0; ks < 8; ks++) {
            qa[ks][mt][0] = f2tf32(q0[ks * 8 + t]     * 0.125f);
            qa[ks][mt][1] = f2tf32(q1[ks * 8 + t]     * 0.125f);
            qa[ks][mt][2] = f2tf32(q0[ks * 8 + t + 4] * 0.125f);
            qa[ks][mt][3] = f2tf32(q1[ks * 8 + t + 4] * 0.125f);
        }
    }

    float o[2][8][4];
#pragma unroll
    for (int mt = 0; mt < 2; mt++)
#pragma unroll
        for (int nt = 0; nt < 8; nt++)
#pragma unroll
            for (int i = 0; i < 4; i++) o[mt][nt][i] = 0.0f;
    float mrow[2][2] = {{-1e30f, -1e30f}, {-1e30f, -1e30f}};
    float lrow[2][2] = {{0.f, 0.f}, {0.f, 0.f}};

    const int j8  = lane & 7;
    const int mtx = lane >> 3;
    const uint32_t ksBase = (uint32_t)__cvta_generic_to_shared(&Ks[0][0]);
    uint32_t kAddr[2];
#pragma unroll
    for (int p = 0; p < 2; p++)
        kAddr[p] = ksBase +
            ((p * 16 + (mtx >> 1) * 8 + j8) * KS_PITCH + (mtx & 1) * 4) * 4;

    const int src0 = (lane & ~3) | (t >> 1);
    const int src2 = src0 + 2;
    const bool odd = (t & 1) != 0;

    for (int kt = 0; kt < 16; kt++) {
        __syncthreads();   // prior chunk's smem reads complete
#pragma unroll
        for (int i = 0; i < 8; i++) {
            const int f4 = tid + i * 128;
            const int rk = f4 >> 4, c4 = f4 & 15;
            const size_t krow = (size_t)(b * NSEQ + kt * 64 + rk) * (3 * DM);
            float4 kv = *(const float4*)(g_qkv + krow + DM     + h * 64 + c4 * 4);
            float4 vv = *(const float4*)(g_qkv + krow + 2 * DM + h * 64 + c4 * 4);
            *(uint4*)&Ks[rk][c4 * 4] = rna4(kv);
            *(uint4*)&Vs[rk][c4 * 4] = rna4(vv);
        }
        __syncthreads();   // tiles ready

#pragma unroll
        for (int c = 0; c < 2; c++) {   // 32-key chunks
            float s[2][4][4];
#pragma unroll
            for (int mt = 0; mt < 2; mt++)
#pragma unroll
                for (int nt = 0; nt < 4; nt++)
#pragma unroll
                    for (int i = 0; i < 4; i++) s[mt][nt][i] = 0.0f;

            // S = Q @ K^T for this chunk
#pragma unroll
            for (int ks = 0; ks < 8; ks++) {
                uint32_t bq[2][4];
#pragma unroll
                for (int p = 0; p < 2; p++)
                    ldsm4(bq[p], kAddr[p] + c * (32 * KS_PITCH * 4) + ks * 32);
#pragma unroll
                for (int mt = 0; mt < 2; mt++) {
                    mma1688(s[mt][0], qa[ks][mt], &bq[0][0]);
                    mma1688(s[mt][1], qa[ks][mt], &bq[0][2]);
                    mma1688(s[mt][2], qa[ks][mt], &bq[1][0]);
                    mma1688(s[mt][3], qa[ks][mt], &bq[1][2]);
                }
            }

            // Online softmax per m-tile
#pragma unroll
            for (int mt = 0; mt < 2; mt++) {
                float tmax0 = -1e30f, tmax1 = -1e30f;
#pragma unroll
                for (int nt = 0; nt < 4; nt++) {
                    tmax0 = fmaxf(tmax0, fmaxf(s[mt][nt][0], s[mt][nt][1]));
                    tmax1 = fmaxf(tmax1, fmaxf(s[mt][nt][2], s[mt][nt][3]));
                }
                tmax0 = fmaxf(tmax0, __shfl_xor_sync(0xffffffffu, tmax0, 1));
                tmax0 = fmaxf(tmax0, __shfl_xor_sync(0xffffffffu, tmax0, 2));
                tmax1 = fmaxf(tmax1, __shfl_xor_sync(0xffffffffu, tmax1, 1));
                tmax1 = fmaxf(tmax1, __shfl_xor_sync(0xffffffffu, tmax1, 2));

                const float mn0 = fmaxf(mrow[mt][0], tmax0);
                const float mn1 = fmaxf(mrow[mt][1], tmax1);
                const float corr0 = __expf(mrow[mt][0] - mn0);
                const float corr1 = __expf(mrow[mt][1] - mn1);

                float sum0 = 0.f, sum1 = 0.f;
#pragma unroll
                for (int nt = 0; nt < 4; nt++) {
                    s[mt][nt][0] = __expf(s[mt][nt][0] - mn0); sum0 += s[mt][nt][0];
                    s[mt][nt][1] = __expf(s[mt][nt][1] - mn0); sum0 += s[mt][nt][1];
                    s[mt][nt][2] = __expf(s[mt][nt][2] - mn1); sum1 += s[mt][nt][2];
                    s[mt][nt][3] = __expf(s[mt][nt][3] - mn1); sum1 += s[mt][nt][3];
                }
                sum0 += __shfl_xor_sync(0xffffffffu, sum0, 1);
                sum0 += __shfl_xor_sync(0xffffffffu, sum0, 2);
                sum1 += __shfl_xor_sync(0xffffffffu, sum1, 1);
                sum1 += __shfl_xor_sync(0xffffffffu, sum1, 2);

                lrow[mt][0] = lrow[mt][0] * corr0 + sum0;
                lrow[mt][1] = lrow[mt][1] * corr1 + sum1;
                mrow[mt][0] = mn0; mrow[mt][1] = mn1;
#pragma unroll
                for (int nt = 0; nt < 8; nt++) {
                    o[mt][nt][0] *= corr0; o[mt][nt][1] *= corr0;
                    o[mt][nt][2] *= corr1; o[mt][nt][3] *= corr1;
                }
            }

            // O += P @ V ; P A-fragments built via shuffles (no smem round-trip)
#pragma unroll
            for (int kv_ = 0; kv_ < 4; kv_++) {
                const int kk = c * 32 + kv_ * 8;
                uint32_t pa[2][4];
#pragma unroll
                for (int mt = 0; mt < 2; mt++) {
                    float v0 = __shfl_sync(0xffffffffu, s[mt][kv_][0], src0);
                    float v1 = __shfl_sync(0xffffffffu, s[mt][kv_][1], src0);
                    float v2 = __shfl_sync(0xffffffffu, s[mt][kv_][2], src0);
                    float v3 = __shfl_sync(0xffffffffu, s[mt][kv_][3], src0);
                    float w0 = __shfl_sync(0xffffffffu, s[mt][kv_][0], src2);
                    float w1 = __shfl_sync(0xffffffffu, s[mt][kv_][1], src2);
                    float w2 = __shfl_sync(0xffffffffu, s[mt][kv_][2], src2);
                    float w3 = __shfl_sync(0xffffffffu, s[mt][kv_][3], src2);
                    pa[mt][0] = __float_as_uint(odd ? v1 : v0);
                    pa[mt][1] = __float_as_uint(odd ? v3 : v2);
                    pa[mt][2] = __float_as_uint(odd ? w1 : w0);
                    pa[mt][3] = __float_as_uint(odd ? w3 : w2);
                }
#pragma unroll
                for (int nt = 0; nt < 8; nt++) {
                    uint32_t bv[2];
                    bv[0] = Vs[kk + t][nt * 8 + g];
                    bv[1] = Vs[kk + t + 4][nt * 8 + g];
                    mma1688(o[0][nt], pa[0], bv);
                    mma1688(o[1][nt], pa[1], bv);
                }
            }
        }
    }

    // Epilogue
#pragma unroll
    for (int mt = 0; mt < 2; mt++) {
        const float inv0 = 1.0f / lrow[mt][0];
        const float inv1 = 1.0f / lrow[mt][1];
        float* op0 = g_attn + (size_t)(qbase + rw + mt * 16 + g) * DM + h * 64;
        float* op1 = op0 + (size_t)8 * DM;
#pragma unroll
        for (int nt = 0; nt < 8; nt++) {
            *(float2*)(op0 + nt * 8 + 2 * t) = make_float2(o[mt][nt][0] * inv0, o[mt][nt][1] * inv0);
            *(float2*)(op1 + nt * 8 + 2 * t) = make_float2(o[mt][nt][2] * inv1, o[mt][nt][3] * inv1);
        }
    }
}

// ---------------------------------------------------------------------------
// Cross-attention: 77 keys. Two-pass softmax. Row-major K/V tiles + float4.
// ---------------------------------------------------------------------------
__global__ void __launch_bounds__(64) cross_attn_kernel()
{
    __shared__ float Kc[TL][64];
    __shared__ float Vc[TL][64];

    const int qt = blockIdx.x, h = blockIdx.y, b = blockIdx.z;
    const int tid = threadIdx.x;

    for (int i = tid; i < TL * 16; i += 64) {
        const int l = i >> 4;
        const int c4 = (i & 15);
        const size_t src = (size_t)(b * TL + l) * DM + h * 64 + c4 * 4;
        ((float4*)Kc[l])[c4] = *(const float4*)(g_kc + src);
        ((float4*)Vc[l])[c4] = *(const float4*)(g_vc + src);
    }
    __syncthreads();

    const int row = b * NSEQ + qt * 64 + tid;
    float q[64];
    {
        const float4* qp = (const float4*)(g_qb + (size_t)row * DM + h * 64);
#pragma unroll
        for (int i = 0; i < 16; i++) {
            float4 tq = qp[i];
            q[4 * i + 0] = tq.x * 0.125f;
            q[4 * i + 1] = tq.y * 0.125f;
            q[4 * i + 2] = tq.z * 0.125f;
            q[4 * i + 3] = tq.w * 0.125f;
        }
    }

    float m = -1e30f;
    for (int l = 0; l < TL; l++) {
        const float4* kr = (const float4*)Kc[l];
        float s0 = 0.f, s1 = 0.f, s2 = 0.f, s3 = 0.f;
#pragma unroll
        for (int i = 0; i < 16; i++) {
            float4 kv = kr[i];
            s0 = fmaf(q[4 * i + 0], kv.x, s0);
            s1 = fmaf(q[4 * i + 1], kv.y, s1);
            s2 = fmaf(q[4 * i + 2], kv.z, s2);
            s3 = fmaf(q[4 * i + 3], kv.w, s3);
        }
        m = fmaxf(m, (s0 + s1) + (s2 + s3));
    }

    float o[64];
#pragma unroll
    for (int d = 0; d < 64; d++) o[d] = 0.0f;
    float lsum = 0.0f;
    for (int l = 0; l < TL; l++) {
        const float4* kr = (const float4*)Kc[l];
        float s0 = 0.f, s1 = 0.f, s2 = 0.f, s3 = 0.f;
#pragma unroll
        for (int i = 0; i < 16; i++) {
            float4 kv = kr[i];
            s0 = fmaf(q[4 * i + 0], kv.x, s0);
            s1 = fmaf(q[4 * i + 1], kv.y, s1);
            s2 = fmaf(q[4 * i + 2], kv.z, s2);
            s3 = fmaf(q[4 * i + 3], kv.w, s3);
        }
        const float p = __expf((s0 + s1) + (s2 + s3) - m);
        lsum += p;
        const float4* vr = (const float4*)Vc[l];
#pragma unroll
        for (int i = 0; i < 16; i++) {
            float4 vv = vr[i];
            o[4 * i + 0] = fmaf(p, vv.x, o[4 * i + 0]);
            o[4 * i + 1] = fmaf(p, vv.y, o[4 * i + 1]);
            o[4 * i + 2] = fmaf(p, vv.z, o[4 * i + 2]);
            o[4 * i + 3] = fmaf(p, vv.w, o[4 * i + 3]);
        }
    }

    const float inv = 1.0f / lsum;
    float4* op = (float4*)(g_attn + (size_t)row * DM + h * 64);
#pragma unroll
    for (int i = 0; i < 16; i++)
        op[i] = make_float4(o[4 * i + 0] * inv, o[4 * i + 1] * inv,
                            o[4 * i + 2] * inv, o[4 * i + 3] * inv);
}

// ---------------------------------------------------------------------------
// Host side
// ---------------------------------------------------------------------------
template <int EPI>
static void launch_gemm(const float* A, const float* W, const float* bias,
                        const float* res, float* C, int M, int N, int K)
{
    dim3 grid(N / 128, (M + 127) / 128);
    tgemm_kernel<EPI><<<grid, 128>>>(A, W, bias, res, C, M, N, K);
}

extern "C" void kernel_launch(void* const* d_in, const int* in_sizes, int n_in,
                              void* d_out, int out_size)
{
    const float* x       = (const float*)d_in[0];
    const float* c       = (const float*)d_in[1];
    const float* text    = (const float*)d_in[2];
    const float* W_ada   = (const float*)d_in[3];
    const float* b_ada   = (const float*)d_in[4];
    const float* W_qkv   = (const float*)d_in[5];
    const float* b_qkv   = (const float*)d_in[6];
    const float* W_proj  = (const float*)d_in[7];
    const float* b_proj  = (const float*)d_in[8];
    const float* W_ctx   = (const float*)d_in[9];
    const float* b_ctx   = (const float*)d_in[10];
    const float* W_q     = (const float*)d_in[11];
    const float* W_k     = (const float*)d_in[12];
    const float* W_v     = (const float*)d_in[13];
    const float* W_out   = (const float*)d_in[14];
    const float* b_out   = (const float*)d_in[15];
    const float* W_fc1   = (const float*)d_in[16];
    const float* b_fc1   = (const float*)d_in[17];
    const float* W_fc2   = (const float*)d_in[18];
    const float* b_fc2   = (const float*)d_in[19];
    float* out = (float*)d_out;

    float *p_h, *p_qkv, *p_attn, *p_x1, *p_x2, *p_ctx, *p_qb, *p_kc, *p_vc, *p_hidden;
    cudaGetSymbolAddress((void**)&p_h,      g_h);
    cudaGetSymbolAddress((void**)&p_qkv,    g_qkv);
    cudaGetSymbolAddress((void**)&p_attn,   g_attn);
    cudaGetSymbolAddress((void**)&p_x1,     g_x1);
    cudaGetSymbolAddress((void**)&p_x2,     g_x2);
    cudaGetSymbolAddress((void**)&p_ctx,    g_ctx);
    cudaGetSymbolAddress((void**)&p_qb,     g_qb);
    cudaGetSymbolAddress((void**)&p_kc,     g_kc);
    cudaGetSymbolAddress((void**)&p_vc,     g_vc);
    cudaGetSymbolAddress((void**)&p_hidden, g_hidden);

    // 1. adaLN modulation
    {
        dim3 grid(6 * DM / 256, BB);
        mod_kernel<<<grid, 256>>>(c, W_ada, b_ada);
    }

    // --- self-attention block ---
    lnmod_kernel<<<TTOK, 256>>>(x, 0 * DM, 1 * DM, p_h);
    launch_gemm<EPI_BIAS>(p_h, W_qkv, b_qkv, nullptr, p_qkv, TTOK, 3 * DM, DM);
    {
        dim3 grid(NSEQ / 128, NH, BB);
        flash_attn_kernel<<<grid, 128>>>();
    }
    launch_gemm<EPI_BIAS_RES>(p_attn, W_proj, b_proj, x, p_x1, TTOK, DM, DM);

    // --- cross-attention block ---
    lnmod_kernel<<<TTOK, 256>>>(p_x1, 2 * DM, 3 * DM, p_h);
    launch_gemm<EPI_BIAS>(text, W_ctx, b_ctx, nullptr, p_ctx, TCTX, DM, TD);
    launch_gemm<EPI_NOBIAS>(p_h, W_q, nullptr, nullptr, p_qb, TTOK, DM, DM);
    launch_gemm<EPI_NOBIAS>(p_ctx, W_k, nullptr, nullptr, p_kc, TCTX, DM, DM);
    launch_gemm<EPI_NOBIAS>(p_ctx, W_v, nullptr, nullptr, p_vc, TCTX, DM, DM);
    {
        dim3 grid(NSEQ / 64, NH, BB);
        cross_attn_kernel<<<grid, 64>>>();
    }
    launch_gemm<EPI_BIAS_RES>(p_attn, W_out, b_out, p_x1, p_x2, TTOK, DM, DM);

    // --- MLP block ---
    lnmod_kernel<<<TTOK, 256>>>(p_x2, 4 * DM, 5 * DM, p_h);
    launch_gemm<EPI_BIAS_GELU>(p_h, W_fc1, b_fc1, nullptr, p_hidden, TTOK, 4 * DM, DM);
    launch_gemm<EPI_BIAS_RES>(p_hidden, W_fc2, b_fc2, p_x2, out, TTOK, DM, 4 * DM);
}

// round 8
// speedup vs baseline: 3.2254x; 1.1116x over previous
#include <cuda_runtime.h>
#include <math.h>
#include <stdint.h>

// ---------------------------------------------------------------------------
// Problem constants
// ---------------------------------------------------------------------------
#define BB 4
#define NSEQ 1024
#define DM 1024
#define NH 16
#define HD 64
#define TD 768
#define TL 77
#define TTOK (BB * NSEQ)   // 4096
#define TCTX (BB * TL)     // 308

// ---------------------------------------------------------------------------
// Scratch (static device globals; no allocation allowed)
// ---------------------------------------------------------------------------
__device__ float g_mod[BB * 6 * DM];
__device__ float g_h[TTOK * DM];
__device__ float g_qkv[TTOK * 3 * DM];
__device__ float g_attn[TTOK * DM];
__device__ float g_x1[TTOK * DM];
__device__ float g_x2[TTOK * DM];
__device__ float g_ctx[TCTX * DM];
__device__ float g_qb[TTOK * DM];
__device__ float g_kc[TCTX * DM];
__device__ float g_vc[TCTX * DM];
__device__ float g_hidden[TTOK * 4 * DM];

// ---------------------------------------------------------------------------
// Helpers
// ---------------------------------------------------------------------------
__device__ __forceinline__ float gelu_tanh(float x) {
    float x3 = x * x * x;
    float t  = tanhf(0.7978845608028654f * (x + 0.044715f * x3));
    return 0.5f * x * (1.0f + t);
}

__device__ __forceinline__ uint32_t f2tf32(float f) {
    uint32_t u;
    asm("cvt.rna.tf32.f32 %0, %1;" : "=r"(u) : "f"(f));
    return u;
}

__device__ __forceinline__ uint4 rna4(float4 v) {
    return make_uint4(f2tf32(v.x), f2tf32(v.y), f2tf32(v.z), f2tf32(v.w));
}

__device__ __forceinline__ void mma1688(float* c, const uint32_t* a, const uint32_t* b) {
    asm volatile(
        "mma.sync.aligned.m16n8k8.row.col.f32.tf32.tf32.f32 "
        "{%0,%1,%2,%3}, {%4,%5,%6,%7}, {%8,%9}, {%0,%1,%2,%3};"
        : "+f"(c[0]), "+f"(c[1]), "+f"(c[2]), "+f"(c[3])
        : "r"(a[0]), "r"(a[1]), "r"(a[2]), "r"(a[3]), "r"(b[0]), "r"(b[1]));
}

__device__ __forceinline__ void ldsm4(uint32_t* r, uint32_t saddr) {
    asm volatile(
        "ldmatrix.sync.aligned.m8n8.x4.shared.b16 {%0,%1,%2,%3}, [%4];"
        : "=r"(r[0]), "=r"(r[1]), "=r"(r[2]), "=r"(r[3]) : "r"(saddr));
}

__device__ __forceinline__ void cpa16(uint32_t dst, const void* src, int srcBytes) {
    asm volatile("cp.async.cg.shared.global [%0], [%1], 16, %2;"
                 :: "r"(dst), "l"(src), "r"(srcBytes));
}
__device__ __forceinline__ void cpa_commit() {
    asm volatile("cp.async.commit_group;");
}
template <int N> __device__ __forceinline__ void cpa_wait() {
    asm volatile("cp.async.wait_group %0;" :: "n"(N));
}

// Epilogue modes
#define EPI_BIAS      0
#define EPI_BIAS_GELU 1
#define EPI_BIAS_RES  2
#define EPI_NOBIAS    3

// ---------------------------------------------------------------------------
// TF32 tensor-core GEMM v3: C[M,N] = A[M,K] @ W[K,N] (+bias)(+gelu)(+res)
// BM=BN=128, BK=16, 128 threads = 4 warps, warp tile 64x64.
// cp.async 2-stage ring of RAW fp32 (no register staging); tf32 RNA conversion
// happens in registers after ldmatrix / LDS. A via ldmatrix.x4 (pitch 20,
// conflict-free), B via scalar LDS ([k][n], pitch 136, conflict-free).
// ---------------------------------------------------------------------------
#define AS_PITCH 20
#define BS_PITCH 136
#define AS_BUFB (128 * AS_PITCH * 4)   // bytes per A stage
#define BS_BUFB (16 * BS_PITCH * 4)    // bytes per B stage

template <int EPI>
__global__ void __launch_bounds__(128) tgemm_kernel(
    const float* __restrict__ A, const float* __restrict__ W,
    const float* __restrict__ bias, const float* __restrict__ res,
    float* __restrict__ C, int M, int N, int K)
{
    __shared__ float As[2][128][AS_PITCH];   // raw fp32 bits
    __shared__ float Bs[2][16][BS_PITCH];

    const int tid  = threadIdx.x;
    const int lane = tid & 31;
    const int warp = tid >> 5;
    const int g = lane >> 2;
    const int t = lane & 3;
    const int wm = (warp & 1) * 64;
    const int wn = (warp >> 1) * 64;
    const int rowBase = blockIdx.y * 128;
    const int colBase = blockIdx.x * 128;

    const uint32_t asBase = (uint32_t)__cvta_generic_to_shared(&As[0][0][0]);
    const uint32_t bsBase = (uint32_t)__cvta_generic_to_shared(&Bs[0][0][0]);

    // per-thread load mapping (4 float4 for A, 4 for B)
    const int ar  = tid >> 2;             // A row (0..31, +32 per i)
    const int ac  = (tid & 3) * 4;        // A k-col
    const int bk  = tid >> 5;             // B k-row (0..3, +4 per i)
    const int bn  = (tid & 31) * 4;       // B n-col

    // ldmatrix A-fragment addresses
    const int j8  = lane & 7;
    const int mtx = lane >> 3;
    uint32_t aAddr[4];
#pragma unroll
    for (int mt = 0; mt < 4; mt++)
        aAddr[mt] = asBase +
            ((wm + mt * 16 + (mtx & 1) * 8 + j8) * AS_PITCH + (mtx >> 1) * 4) * 4;

    float acc[4][8][4];
#pragma unroll
    for (int mt = 0; mt < 4; mt++)
#pragma unroll
        for (int nt = 0; nt < 8; nt++)
#pragma unroll
            for (int i = 0; i < 4; i++) acc[mt][nt][i] = 0.0f;

    // stage loader: raw fp32 gmem -> smem via cp.async
    auto issueStage = [&](int stage, int k0) {
#pragma unroll
        for (int i = 0; i < 4; i++) {
            const int r = ar + i * 32;
            const int row = rowBase + r;
            const int rowC = (row < M) ? row : 0;
            cpa16(asBase + (uint32_t)stage * AS_BUFB + (r * AS_PITCH + ac) * 4,
                  A + (size_t)rowC * K + k0 + ac, (row < M) ? 16 : 0);
            const int kk = bk + i * 4;
            cpa16(bsBase + (uint32_t)stage * BS_BUFB + (kk * BS_PITCH + bn) * 4,
                  W + (size_t)(k0 + kk) * N + colBase + bn, 16);
        }
        cpa_commit();
    };

    issueStage(0, 0);

    int buf = 0;
    for (int k0 = 0; k0 < K; k0 += 16) {
        const bool hasNext = (k0 + 16) < K;
        if (hasNext) {
            issueStage(buf ^ 1, k0 + 16);
            cpa_wait<1>();
        } else {
            cpa_wait<0>();
        }
        __syncthreads();   // stage 'buf' visible to all warps

        const uint32_t aOff = (uint32_t)buf * AS_BUFB;
        const float* __restrict__ bsBuf = &Bs[buf][0][0];
#pragma unroll
        for (int ks = 0; ks < 16; ks += 8) {
            uint32_t af[4][4];
#pragma unroll
            for (int mt = 0; mt < 4; mt++) {
                ldsm4(af[mt], aAddr[mt] + aOff + ks * 4);
#pragma unroll
                for (int i = 0; i < 4; i++)
                    af[mt][i] = f2tf32(__uint_as_float(af[mt][i]));
            }
            uint32_t bf[8][2];
#pragma unroll
            for (int nt = 0; nt < 8; nt++) {
                bf[nt][0] = f2tf32(bsBuf[(ks + t)     * BS_PITCH + wn + nt * 8 + g]);
                bf[nt][1] = f2tf32(bsBuf[(ks + t + 4) * BS_PITCH + wn + nt * 8 + g]);
            }
#pragma unroll
            for (int mt = 0; mt < 4; mt++)
#pragma unroll
                for (int nt = 0; nt < 8; nt++)
                    mma1688(acc[mt][nt], af[mt], bf[nt]);
        }
        __syncthreads();   // all warps done reading 'buf' before next overwrite
        buf ^= 1;
    }

    // Epilogue
#pragma unroll
    for (int mt = 0; mt < 4; mt++) {
        const int row0 = rowBase + wm + mt * 16 + g;
        const int row1 = row0 + 8;
#pragma unroll
        for (int nt = 0; nt < 8; nt++) {
            const int col = colBase + wn + nt * 8 + t * 2;
            float b0 = 0.f, b1 = 0.f;
            if (EPI != EPI_NOBIAS) { b0 = bias[col]; b1 = bias[col + 1]; }
            float v0 = acc[mt][nt][0] + b0;
            float v1 = acc[mt][nt][1] + b1;
            float v2 = acc[mt][nt][2] + b0;
            float v3 = acc[mt][nt][3] + b1;
            if (EPI == EPI_BIAS_GELU) {
                v0 = gelu_tanh(v0); v1 = gelu_tanh(v1);
                v2 = gelu_tanh(v2); v3 = gelu_tanh(v3);
            }
            if (row0 < M) {
                if (EPI == EPI_BIAS_RES) {
                    float2 r = *(const float2*)(res + (size_t)row0 * N + col);
                    v0 += r.x; v1 += r.y;
                }
                *(float2*)(C + (size_t)row0 * N + col) = make_float2(v0, v1);
            }
            if (row1 < M) {
                if (EPI == EPI_BIAS_RES) {
                    float2 r = *(const float2*)(res + (size_t)row1 * N + col);
                    v2 += r.x; v3 += r.y;
                }
                *(float2*)(C + (size_t)row1 * N + col) = make_float2(v2, v3);
            }
        }
    }
}

// ---------------------------------------------------------------------------
// adaLN modulation
// ---------------------------------------------------------------------------
__global__ void __launch_bounds__(256) mod_kernel(
    const float* __restrict__ c, const float* __restrict__ W,
    const float* __restrict__ bias)
{
    const int b = blockIdx.y;
    const int col = blockIdx.x * 256 + threadIdx.x;
    __shared__ float sc[DM];
    for (int i = threadIdx.x; i < DM; i += 256) {
        float v = c[b * DM + i];
        sc[i] = v / (1.0f + __expf(-v));
    }
    __syncthreads();
    float acc = 0.0f;
#pragma unroll 8
    for (int k = 0; k < DM; k++)
        acc = fmaf(sc[k], W[(size_t)k * (6 * DM) + col], acc);
    g_mod[b * 6 * DM + col] = acc + bias[col];
}

// ---------------------------------------------------------------------------
// LayerNorm + modulate
// ---------------------------------------------------------------------------
__global__ void __launch_bounds__(256) lnmod_kernel(
    const float* __restrict__ x, int shOff, int scOff, float* __restrict__ out)
{
    const int row = blockIdx.x;
    const int b = row >> 10;
    const int tid = threadIdx.x;

    float4 v = ((const float4*)(x + (size_t)row * DM))[tid];
    float s  = v.x + v.y + v.z + v.w;
    float s2 = v.x * v.x + v.y * v.y + v.z * v.z + v.w * v.w;

    __shared__ float red[16];
#pragma unroll
    for (int off = 16; off > 0; off >>= 1) {
        s  += __shfl_xor_sync(0xffffffffu, s,  off);
        s2 += __shfl_xor_sync(0xffffffffu, s2, off);
    }
    const int warp = tid >> 5, lane = tid & 31;
    if (lane == 0) { red[warp] = s; red[warp + 8] = s2; }
    __syncthreads();
    if (tid == 0) {
        float ts = 0.f, ts2 = 0.f;
#pragma unroll
        for (int i = 0; i < 8; i++) { ts += red[i]; ts2 += red[i + 8]; }
        float mu  = ts * (1.0f / DM);
        float var = ts2 * (1.0f / DM) - mu * mu;
        red[0] = mu;
        red[1] = rsqrtf(var + 1e-6f);
    }
    __syncthreads();
    const float mu = red[0], rs = red[1];

    const float* modp = g_mod + b * 6 * DM;
    const int cc = tid * 4;
    float4 sh  = *(const float4*)(modp + shOff + cc);
    float4 scv = *(const float4*)(modp + scOff + cc);
    float4 o;
    o.x = (v.x - mu) * rs * (1.0f + scv.x) + sh.x;
    o.y = (v.y - mu) * rs * (1.0f + scv.y) + sh.y;
    o.z = (v.z - mu) * rs * (1.0f + scv.z) + sh.z;
    o.w = (v.w - mu) * rs * (1.0f + scv.w) + sh.w;
    ((float4*)(out + (size_t)row * DM))[tid] = o;
}

// ---------------------------------------------------------------------------
// Tensor-core flash self-attention v2 (unchanged from round 7 — passing).
// ---------------------------------------------------------------------------
#define KS_PITCH 76
#define VS_PITCH 88

__global__ void __launch_bounds__(128) flash_attn_kernel()
{
    __shared__ uint32_t Ks[64][KS_PITCH];
    __shared__ uint32_t Vs[64][VS_PITCH];

    const int qt = blockIdx.x, h = blockIdx.y, b = blockIdx.z;
    const int tid  = threadIdx.x;
    const int lane = tid & 31;
    const int warp = tid >> 5;
    const int g = lane >> 2;
    const int t = lane & 3;
    const int rw = warp * 32;
    const int qbase = b * NSEQ + qt * 128;

    uint32_t qa[8][2][4];
#pragma unroll
    for (int mt = 0; mt < 2; mt++) {
        const float* q0 = g_qkv + (size_t)(qbase + rw + mt * 16 + g) * (3 * DM) + h * 64;
        const float* q1 = q0 + (size_t)8 * (3 * DM);
#pragma unroll
        for (int ks = 0; ks < 8; ks++) {
            qa[ks][mt][0] = f2tf32(q0[ks * 8 + t]     * 0.125f);
            qa[ks][mt][1] = f2tf32(q1[ks * 8 + t]     * 0.125f);
            qa[ks][mt][2] = f2tf32(q0[ks * 8 + t + 4] * 0.125f);
            qa[ks][mt][3] = f2tf32(q1[ks * 8 + t + 4] * 0.125f);
        }
    }

    float o[2][8][4];
#pragma unroll
    for (int mt = 0; mt < 2; mt++)
#pragma unroll
        for (int nt = 0; nt < 8; nt++)
#pragma unroll
            for (int i = 0; i < 4; i++) o[mt][nt][i] = 0.0f;
    float mrow[2][2] = {{-1e30f, -1e30f}, {-1e30f, -1e30f}};
    float lrow[2][2] = {{0.f, 0.f}, {0.f, 0.f}};

    const int j8  = lane & 7;
    const int mtx = lane >> 3;
    const uint32_t ksBase = (uint32_t)__cvta_generic_to_shared(&Ks[0][0]);
    uint32_t kAddr[2];
#pragma unroll
    for (int p = 0; p < 2; p++)
        kAddr[p] = ksBase +
            ((p * 16 + (mtx >> 1) * 8 + j8) * KS_PITCH + (mtx & 1) * 4) * 4;

    const int src0 = (lane & ~3) | (t >> 1);
    const int src2 = src0 + 2;
    const bool odd = (t & 1) != 0;

    for (int kt = 0; kt < 16; kt++) {
        __syncthreads();
#pragma unroll
        for (int i = 0; i < 8; i++) {
            const int f4 = tid + i * 128;
            const int rk = f4 >> 4, c4 = f4 & 15;
            const size_t krow = (size_t)(b * NSEQ + kt * 64 + rk) * (3 * DM);
            float4 kv = *(const float4*)(g_qkv + krow + DM     + h * 64 + c4 * 4);
            float4 vv = *(const float4*)(g_qkv + krow + 2 * DM + h * 64 + c4 * 4);
            *(uint4*)&Ks[rk][c4 * 4] = rna4(kv);
            *(uint4*)&Vs[rk][c4 * 4] = rna4(vv);
        }
        __syncthreads();

#pragma unroll
        for (int c = 0; c < 2; c++) {
            float s[2][4][4];
#pragma unroll
            for (int mt = 0; mt < 2; mt++)
#pragma unroll
                for (int nt = 0; nt < 4; nt++)
#pragma unroll
                    for (int i = 0; i < 4; i++) s[mt][nt][i] = 0.0f;

#pragma unroll
            for (int ks = 0; ks < 8; ks++) {
                uint32_t bq[2][4];
#pragma unroll
                for (int p = 0; p < 2; p++)
                    ldsm4(bq[p], kAddr[p] + c * (32 * KS_PITCH * 4) + ks * 32);
#pragma unroll
                for (int mt = 0; mt < 2; mt++) {
                    mma1688(s[mt][0], qa[ks][mt], &bq[0][0]);
                    mma1688(s[mt][1], qa[ks][mt], &bq[0][2]);
                    mma1688(s[mt][2], qa[ks][mt], &bq[1][0]);
                    mma1688(s[mt][3], qa[ks][mt], &bq[1][2]);
                }
            }

#pragma unroll
            for (int mt = 0; mt < 2; mt++) {
                float tmax0 = -1e30f, tmax1 = -1e30f;
#pragma unroll
                for (int nt = 0; nt < 4; nt++) {
                    tmax0 = fmaxf(tmax0, fmaxf(s[mt][nt][0], s[mt][nt][1]));
                    tmax1 = fmaxf(tmax1, fmaxf(s[mt][nt][2], s[mt][nt][3]));
                }
                tmax0 = fmaxf(tmax0, __shfl_xor_sync(0xffffffffu, tmax0, 1));
                tmax0 = fmaxf(tmax0, __shfl_xor_sync(0xffffffffu, tmax0, 2));
                tmax1 = fmaxf(tmax1, __shfl_xor_sync(0xffffffffu, tmax1, 1));
                tmax1 = fmaxf(tmax1, __shfl_xor_sync(0xffffffffu, tmax1, 2));

                const float mn0 = fmaxf(mrow[mt][0], tmax0);
                const float mn1 = fmaxf(mrow[mt][1], tmax1);
                const float corr0 = __expf(mrow[mt][0] - mn0);
                const float corr1 = __expf(mrow[mt][1] - mn1);

                float sum0 = 0.f, sum1 = 0.f;
#pragma unroll
                for (int nt = 0; nt < 4; nt++) {
                    s[mt][nt][0] = __expf(s[mt][nt][0] - mn0); sum0 += s[mt][nt][0];
                    s[mt][nt][1] = __expf(s[mt][nt][1] - mn0); sum0 += s[mt][nt][1];
                    s[mt][nt][2] = __expf(s[mt][nt][2] - mn1); sum1 += s[mt][nt][2];
                    s[mt][nt][3] = __expf(s[mt][nt][3] - mn1); sum1 += s[mt][nt][3];
                }
                sum0 += __shfl_xor_sync(0xffffffffu, sum0, 1);
                sum0 += __shfl_xor_sync(0xffffffffu, sum0, 2);
                sum1 += __shfl_xor_sync(0xffffffffu, sum1, 1);
                sum1 += __shfl_xor_sync(0xffffffffu, sum1, 2);

                lrow[mt][0] = lrow[mt][0] * corr0 + sum0;
                lrow[mt][1] = lrow[mt][1] * corr1 + sum1;
                mrow[mt][0] = mn0; mrow[mt][1] = mn1;
#pragma unroll
                for (int nt = 0; nt < 8; nt++) {
                    o[mt][nt][0] *= corr0; o[mt][nt][1] *= corr0;
                    o[mt][nt][2] *= corr1; o[mt][nt][3] *= corr1;
                }
            }

#pragma unroll
            for (int kv_ = 0; kv_ < 4; kv_++) {
                const int kk = c * 32 + kv_ * 8;
                uint32_t pa[2][4];
#pragma unroll
                for (int mt = 0; mt < 2; mt++) {
                    float v0 = __shfl_sync(0xffffffffu, s[mt][kv_][0], src0);
                    float v1 = __shfl_sync(0xffffffffu, s[mt][kv_][1], src0);
                    float v2 = __shfl_sync(0xffffffffu, s[mt][kv_][2], src0);
                    float v3 = __shfl_sync(0xffffffffu, s[mt][kv_][3], src0);
                    float w0 = __shfl_sync(0xffffffffu, s[mt][kv_][0], src2);
                    float w1 = __shfl_sync(0xffffffffu, s[mt][kv_][1], src2);
                    float w2 = __shfl_sync(0xffffffffu, s[mt][kv_][2], src2);
                    float w3 = __shfl_sync(0xffffffffu, s[mt][kv_][3], src2);
                    pa[mt][0] = __float_as_uint(odd ? v1 : v0);
                    pa[mt][1] = __float_as_uint(odd ? v3 : v2);
                    pa[mt][2] = __float_as_uint(odd ? w1 : w0);
                    pa[mt][3] = __float_as_uint(odd ? w3 : w2);
                }
#pragma unroll
                for (int nt = 0; nt < 8; nt++) {
                    uint32_t bv[2];
                    bv[0] = Vs[kk + t][nt * 8 + g];
                    bv[1] = Vs[kk + t + 4][nt * 8 + g];
                    mma1688(o[0][nt], pa[0], bv);
                    mma1688(o[1][nt], pa[1], bv);
                }
            }
        }
    }

#pragma unroll
    for (int mt = 0; mt < 2; mt++) {
        const float inv0 = 1.0f / lrow[mt][0];
        const float inv1 = 1.0f / lrow[mt][1];
        float* op0 = g_attn + (size_t)(qbase + rw + mt * 16 + g) * DM + h * 64;
        float* op1 = op0 + (size_t)8 * DM;
#pragma unroll
        for (int nt = 0; nt < 8; nt++) {
            *(float2*)(op0 + nt * 8 + 2 * t) = make_float2(o[mt][nt][0] * inv0, o[mt][nt][1] * inv0);
            *(float2*)(op1 + nt * 8 + 2 * t) = make_float2(o[mt][nt][2] * inv1, o[mt][nt][3] * inv1);
        }
    }
}

// ---------------------------------------------------------------------------
// Cross-attention: 77 keys. Two-pass softmax. Row-major K/V tiles + float4.
// ---------------------------------------------------------------------------
__global__ void __launch_bounds__(64) cross_attn_kernel()
{
    __shared__ float Kc[TL][64];
    __shared__ float Vc[TL][64];

    const int qt = blockIdx.x, h = blockIdx.y, b = blockIdx.z;
    const int tid = threadIdx.x;

    for (int i = tid; i < TL * 16; i += 64) {
        const int l = i >> 4;
        const int c4 = (i & 15);
        const size_t src = (size_t)(b * TL + l) * DM + h * 64 + c4 * 4;
        ((float4*)Kc[l])[c4] = *(const float4*)(g_kc + src);
        ((float4*)Vc[l])[c4] = *(const float4*)(g_vc + src);
    }
    __syncthreads();

    const int row = b * NSEQ + qt * 64 + tid;
    float q[64];
    {
        const float4* qp = (const float4*)(g_qb + (size_t)row * DM + h * 64);
#pragma unroll
        for (int i = 0; i < 16; i++) {
            float4 tq = qp[i];
            q[4 * i + 0] = tq.x * 0.125f;
            q[4 * i + 1] = tq.y * 0.125f;
            q[4 * i + 2] = tq.z * 0.125f;
            q[4 * i + 3] = tq.w * 0.125f;
        }
    }

    float m = -1e30f;
    for (int l = 0; l < TL; l++) {
        const float4* kr = (const float4*)Kc[l];
        float s0 = 0.f, s1 = 0.f, s2 = 0.f, s3 = 0.f;
#pragma unroll
        for (int i = 0; i < 16; i++) {
            float4 kv = kr[i];
            s0 = fmaf(q[4 * i + 0], kv.x, s0);
            s1 = fmaf(q[4 * i + 1], kv.y, s1);
            s2 = fmaf(q[4 * i + 2], kv.z, s2);
            s3 = fmaf(q[4 * i + 3], kv.w, s3);
        }
        m = fmaxf(m, (s0 + s1) + (s2 + s3));
    }

    float o[64];
#pragma unroll
    for (int d = 0; d < 64; d++) o[d] = 0.0f;
    float lsum = 0.0f;
    for (int l = 0; l < TL; l++) {
        const float4* kr = (const float4*)Kc[l];
        float s0 = 0.f, s1 = 0.f, s2 = 0.f, s3 = 0.f;
#pragma unroll
        for (int i = 0; i < 16; i++) {
            float4 kv = kr[i];
            s0 = fmaf(q[4 * i + 0], kv.x, s0);
            s1 = fmaf(q[4 * i + 1], kv.y, s1);
            s2 = fmaf(q[4 * i + 2], kv.z, s2);
            s3 = fmaf(q[4 * i + 3], kv.w, s3);
        }
        const float p = __expf((s0 + s1) + (s2 + s3) - m);
        lsum += p;
        const float4* vr = (const float4*)Vc[l];
#pragma unroll
        for (int i = 0; i < 16; i++) {
            float4 vv = vr[i];
            o[4 * i + 0] = fmaf(p, vv.x, o[4 * i + 0]);
            o[4 * i + 1] = fmaf(p, vv.y, o[4 * i + 1]);
            o[4 * i + 2] = fmaf(p, vv.z, o[4 * i + 2]);
            o[4 * i + 3] = fmaf(p, vv.w, o[4 * i + 3]);
        }
    }

    const float inv = 1.0f / lsum;
    float4* op = (float4*)(g_attn + (size_t)row * DM + h * 64);
#pragma unroll
    for (int i = 0; i < 16; i++)
        op[i] = make_float4(o[4 * i + 0] * inv, o[4 * i + 1] * inv,
                            o[4 * i + 2] * inv, o[4 * i + 3] * inv);
}

// ---------------------------------------------------------------------------
// Host side
// ---------------------------------------------------------------------------
template <int EPI>
static void launch_gemm(const float* A, const float* W, const float* bias,
                        const float* res, float* C, int M, int N, int K)
{
    dim3 grid(N / 128, (M + 127) / 128);
    tgemm_kernel<EPI><<<grid, 128>>>(A, W, bias, res, C, M, N, K);
}

extern "C" void kernel_launch(void* const* d_in, const int* in_sizes, int n_in,
                              void* d_out, int out_size)
{
    const float* x       = (const float*)d_in[0];
    const float* c       = (const float*)d_in[1];
    const float* text    = (const float*)d_in[2];
    const float* W_ada   = (const float*)d_in[3];
    const float* b_ada   = (const float*)d_in[4];
    const float* W_qkv   = (const float*)d_in[5];
    const float* b_qkv   = (const float*)d_in[6];
    const float* W_proj  = (const float*)d_in[7];
    const float* b_proj  = (const float*)d_in[8];
    const float* W_ctx   = (const float*)d_in[9];
    const float* b_ctx   = (const float*)d_in[10];
    const float* W_q     = (const float*)d_in[11];
    const float* W_k     = (const float*)d_in[12];
    const float* W_v     = (const float*)d_in[13];
    const float* W_out   = (const float*)d_in[14];
    const float* b_out   = (const float*)d_in[15];
    const float* W_fc1   = (const float*)d_in[16];
    const float* b_fc1   = (const float*)d_in[17];
    const float* W_fc2   = (const float*)d_in[18];
    const float* b_fc2   = (const float*)d_in[19];
    float* out = (float*)d_out;

    float *p_h, *p_qkv, *p_attn, *p_x1, *p_x2, *p_ctx, *p_qb, *p_kc, *p_vc, *p_hidden;
    cudaGetSymbolAddress((void**)&p_h,      g_h);
    cudaGetSymbolAddress((void**)&p_qkv,    g_qkv);
    cudaGetSymbolAddress((void**)&p_attn,   g_attn);
    cudaGetSymbolAddress((void**)&p_x1,     g_x1);
    cudaGetSymbolAddress((void**)&p_x2,     g_x2);
    cudaGetSymbolAddress((void**)&p_ctx,    g_ctx);
    cudaGetSymbolAddress((void**)&p_qb,     g_qb);
    cudaGetSymbolAddress((void**)&p_kc,     g_kc);
    cudaGetSymbolAddress((void**)&p_vc,     g_vc);
    cudaGetSymbolAddress((void**)&p_hidden, g_hidden);

    // 1. adaLN modulation
    {
        dim3 grid(6 * DM / 256, BB);
        mod_kernel<<<grid, 256>>>(c, W_ada, b_ada);
    }

    // --- self-attention block ---
    lnmod_kernel<<<TTOK, 256>>>(x, 0 * DM, 1 * DM, p_h);
    launch_gemm<EPI_BIAS>(p_h, W_qkv, b_qkv, nullptr, p_qkv, TTOK, 3 * DM, DM);
    {
        dim3 grid(NSEQ / 128, NH, BB);
        flash_attn_kernel<<<grid, 128>>>();
    }
    launch_gemm<EPI_BIAS_RES>(p_attn, W_proj, b_proj, x, p_x1, TTOK, DM, DM);

    // --- cross-attention block ---
    lnmod_kernel<<<TTOK, 256>>>(p_x1, 2 * DM, 3 * DM, p_h);
    launch_gemm<EPI_BIAS>(text, W_ctx, b_ctx, nullptr, p_ctx, TCTX, DM, TD);
    launch_gemm<EPI_NOBIAS>(p_h, W_q, nullptr, nullptr, p_qb, TTOK, DM, DM);
    launch_gemm<EPI_NOBIAS>(p_ctx, W_k, nullptr, nullptr, p_kc, TCTX, DM, DM);
    launch_gemm<EPI_NOBIAS>(p_ctx, W_v, nullptr, nullptr, p_vc, TCTX, DM, DM);
    {
        dim3 grid(NSEQ / 64, NH, BB);
        cross_attn_kernel<<<grid, 64>>>();
    }
    launch_gemm<EPI_BIAS_RES>(p_attn, W_out, b_out, p_x1, p_x2, TTOK, DM, DM);

    // --- MLP block ---
    lnmod_kernel<<<TTOK, 256>>>(p_x2, 4 * DM, 5 * DM, p_h);
    launch_gemm<EPI_BIAS_GELU>(p_h, W_fc1, b_fc1, nullptr, p_hidden, TTOK, 4 * DM, DM);
    launch_gemm<EPI_BIAS_RES>(p_hidden, W_fc2, b_fc2, p_x2, out, TTOK, DM, 4 * DM);
}

// round 9
// speedup vs baseline: 3.4809x; 1.0792x over previous
#include <cuda_runtime.h>
#include <math.h>
#include <stdint.h>

// ---------------------------------------------------------------------------
// Problem constants
// ---------------------------------------------------------------------------
#define BB 4
#define NSEQ 1024
#define DM 1024
#define NH 16
#define HD 64
#define TD 768
#define TL 77
#define TTOK (BB * NSEQ)   // 4096
#define TCTX (BB * TL)     // 308

// ---------------------------------------------------------------------------
// Scratch (static device globals; no allocation allowed)
// ---------------------------------------------------------------------------
__device__ float g_mod[BB * 6 * DM];
__device__ float g_h[TTOK * DM];
__device__ float g_qkv[TTOK * 3 * DM];
__device__ float g_attn[TTOK * DM];
__device__ float g_x1[TTOK * DM];
__device__ float g_x2[TTOK * DM];
__device__ float g_ctx[TCTX * DM];
__device__ float g_qb[TTOK * DM];
__device__ float g_kc[TCTX * DM];
__device__ float g_vc[TCTX * DM];
__device__ float g_hidden[TTOK * 4 * DM];

// Pre-converted (tf32-rounded) weights + text, one big segment buffer.
#define OFF_QKV  0u
#define OFF_PROJ (OFF_QKV  + 1024u * 3072u)
#define OFF_CTX  (OFF_PROJ + 1024u * 1024u)
#define OFF_Q    (OFF_CTX  + 768u * 1024u)
#define OFF_K    (OFF_Q    + 1024u * 1024u)
#define OFF_V    (OFF_K    + 1024u * 1024u)
#define OFF_OUT  (OFF_V    + 1024u * 1024u)
#define OFF_FC1  (OFF_OUT  + 1024u * 1024u)
#define OFF_FC2  (OFF_FC1  + 1024u * 4096u)
#define OFF_TEXT (OFF_FC2  + 4096u * 1024u)
#define WC_TOTAL (OFF_TEXT + (uint32_t)(BB * TL * TD))
__device__ uint32_t g_wc[WC_TOTAL];

// ---------------------------------------------------------------------------
// Helpers
// ---------------------------------------------------------------------------
__device__ __forceinline__ float gelu_tanh(float x) {
    float x3 = x * x * x;
    float t  = tanhf(0.7978845608028654f * (x + 0.044715f * x3));
    return 0.5f * x * (1.0f + t);
}

__device__ __forceinline__ uint32_t f2tf32(float f) {
    uint32_t u;
    asm("cvt.rna.tf32.f32 %0, %1;" : "=r"(u) : "f"(f));
    return u;
}
__device__ __forceinline__ float rnaf(float f) {
    return __uint_as_float(f2tf32(f));
}
__device__ __forceinline__ uint4 rna4(float4 v) {
    return make_uint4(f2tf32(v.x), f2tf32(v.y), f2tf32(v.z), f2tf32(v.w));
}

__device__ __forceinline__ void mma1688(float* c, const uint32_t* a, const uint32_t* b) {
    asm volatile(
        "mma.sync.aligned.m16n8k8.row.col.f32.tf32.tf32.f32 "
        "{%0,%1,%2,%3}, {%4,%5,%6,%7}, {%8,%9}, {%0,%1,%2,%3};"
        : "+f"(c[0]), "+f"(c[1]), "+f"(c[2]), "+f"(c[3])
        : "r"(a[0]), "r"(a[1]), "r"(a[2]), "r"(a[3]), "r"(b[0]), "r"(b[1]));
}

__device__ __forceinline__ void ldsm4(uint32_t* r, uint32_t saddr) {
    asm volatile(
        "ldmatrix.sync.aligned.m8n8.x4.shared.b16 {%0,%1,%2,%3}, [%4];"
        : "=r"(r[0]), "=r"(r[1]), "=r"(r[2]), "=r"(r[3]) : "r"(saddr));
}

__device__ __forceinline__ void cpa16(uint32_t dst, const void* src, int srcBytes) {
    asm volatile("cp.async.cg.shared.global [%0], [%1], 16, %2;"
                 :: "r"(dst), "l"(src), "r"(srcBytes));
}
__device__ __forceinline__ void cpa_commit() {
    asm volatile("cp.async.commit_group;");
}
template <int N> __device__ __forceinline__ void cpa_wait() {
    asm volatile("cp.async.wait_group %0;" :: "n"(N));
}

// ---------------------------------------------------------------------------
// tf32 pre-convert kernel (RNA round, vectorized)
// ---------------------------------------------------------------------------
__global__ void __launch_bounds__(256) cvt_kernel(
    const float* __restrict__ src, uint32_t* __restrict__ dst, int n)
{
    const int i = (blockIdx.x * 256 + threadIdx.x) * 4;
    if (i < n) {
        float4 v = *(const float4*)(src + i);
        *(uint4*)(dst + i) = rna4(v);
    }
}

// Epilogue modes
#define EPI_BIAS      0
#define EPI_BIAS_GELU 1
#define EPI_BIAS_RES  2
#define EPI_NOBIAS    3

// ---------------------------------------------------------------------------
// TF32 tensor-core GEMM v4: C[M,N] = A[M,K] @ W[K,N] (+bias)(+gelu)(+res)
// A: fp32 pre-rounded to tf32 at the producer; W: tf32 bits (g_wc).
// ZERO cvts in the mainloop — ldmatrix/LDS feed MMAs directly.
// BM=BN=128, BK=16, 128 threads = 4 warps, warp tile 64x64.
// cp.async 2-stage ring. A via ldmatrix.x4 (pitch 20), B via LDS (pitch 136).
// ROUND: store outputs rounded to tf32 (for tensors feeding later GEMMs).
// ---------------------------------------------------------------------------
#define AS_PITCH 20
#define BS_PITCH 136
#define AS_BUFB (128 * AS_PITCH * 4)
#define BS_BUFB (16 * BS_PITCH * 4)

template <int EPI, bool ROUND>
__global__ void __launch_bounds__(128) tgemm_kernel(
    const float* __restrict__ A, const uint32_t* __restrict__ W,
    const float* __restrict__ bias, const float* __restrict__ res,
    float* __restrict__ C, int M, int N, int K)
{
    __shared__ uint32_t As[2][128][AS_PITCH];
    __shared__ uint32_t Bs[2][16][BS_PITCH];

    const int tid  = threadIdx.x;
    const int lane = tid & 31;
    const int warp = tid >> 5;
    const int g = lane >> 2;
    const int t = lane & 3;
    const int wm = (warp & 1) * 64;
    const int wn = (warp >> 1) * 64;
    const int rowBase = blockIdx.y * 128;
    const int colBase = blockIdx.x * 128;

    const uint32_t asBase = (uint32_t)__cvta_generic_to_shared(&As[0][0][0]);
    const uint32_t bsBase = (uint32_t)__cvta_generic_to_shared(&Bs[0][0][0]);

    const int ar  = tid >> 2;
    const int ac  = (tid & 3) * 4;
    const int bk  = tid >> 5;
    const int bn  = (tid & 31) * 4;

    const int j8  = lane & 7;
    const int mtx = lane >> 3;
    uint32_t aAddr[4];
#pragma unroll
    for (int mt = 0; mt < 4; mt++)
        aAddr[mt] = asBase +
            ((wm + mt * 16 + (mtx & 1) * 8 + j8) * AS_PITCH + (mtx >> 1) * 4) * 4;

    float acc[4][8][4];
#pragma unroll
    for (int mt = 0; mt < 4; mt++)
#pragma unroll
        for (int nt = 0; nt < 8; nt++)
#pragma unroll
            for (int i = 0; i < 4; i++) acc[mt][nt][i] = 0.0f;

    auto issueStage = [&](int stage, int k0) {
#pragma unroll
        for (int i = 0; i < 4; i++) {
            const int r = ar + i * 32;
            const int row = rowBase + r;
            const int rowC = (row < M) ? row : 0;
            cpa16(asBase + (uint32_t)stage * AS_BUFB + (r * AS_PITCH + ac) * 4,
                  A + (size_t)rowC * K + k0 + ac, (row < M) ? 16 : 0);
            const int kk = bk + i * 4;
            cpa16(bsBase + (uint32_t)stage * BS_BUFB + (kk * BS_PITCH + bn) * 4,
                  W + (size_t)(k0 + kk) * N + colBase + bn, 16);
        }
        cpa_commit();
    };

    issueStage(0, 0);

    int buf = 0;
    for (int k0 = 0; k0 < K; k0 += 16) {
        const bool hasNext = (k0 + 16) < K;
        if (hasNext) {
            issueStage(buf ^ 1, k0 + 16);
            cpa_wait<1>();
        } else {
            cpa_wait<0>();
        }
        __syncthreads();

        const uint32_t aOff = (uint32_t)buf * AS_BUFB;
        const uint32_t* __restrict__ bsBuf = &Bs[buf][0][0];
#pragma unroll
        for (int ks = 0; ks < 16; ks += 8) {
            uint32_t af[4][4];
#pragma unroll
            for (int mt = 0; mt < 4; mt++)
                ldsm4(af[mt], aAddr[mt] + aOff + ks * 4);
            uint32_t bf[8][2];
#pragma unroll
            for (int nt = 0; nt < 8; nt++) {
                bf[nt][0] = bsBuf[(ks + t)     * BS_PITCH + wn + nt * 8 + g];
                bf[nt][1] = bsBuf[(ks + t + 4) * BS_PITCH + wn + nt * 8 + g];
            }
#pragma unroll
            for (int mt = 0; mt < 4; mt++)
#pragma unroll
                for (int nt = 0; nt < 8; nt++)
                    mma1688(acc[mt][nt], af[mt], bf[nt]);
        }
        __syncthreads();
        buf ^= 1;
    }

    // Epilogue
#pragma unroll
    for (int mt = 0; mt < 4; mt++) {
        const int row0 = rowBase + wm + mt * 16 + g;
        const int row1 = row0 + 8;
#pragma unroll
        for (int nt = 0; nt < 8; nt++) {
            const int col = colBase + wn + nt * 8 + t * 2;
            float b0 = 0.f, b1 = 0.f;
            if (EPI != EPI_NOBIAS) { b0 = bias[col]; b1 = bias[col + 1]; }
            float v0 = acc[mt][nt][0] + b0;
            float v1 = acc[mt][nt][1] + b1;
            float v2 = acc[mt][nt][2] + b0;
            float v3 = acc[mt][nt][3] + b1;
            if (EPI == EPI_BIAS_GELU) {
                v0 = gelu_tanh(v0); v1 = gelu_tanh(v1);
                v2 = gelu_tanh(v2); v3 = gelu_tanh(v3);
            }
            if (ROUND) {
                v0 = rnaf(v0); v1 = rnaf(v1); v2 = rnaf(v2); v3 = rnaf(v3);
            }
            if (row0 < M) {
                if (EPI == EPI_BIAS_RES) {
                    float2 r = *(const float2*)(res + (size_t)row0 * N + col);
                    v0 += r.x; v1 += r.y;
                }
                *(float2*)(C + (size_t)row0 * N + col) = make_float2(v0, v1);
            }
            if (row1 < M) {
                if (EPI == EPI_BIAS_RES) {
                    float2 r = *(const float2*)(res + (size_t)row1 * N + col);
                    v2 += r.x; v3 += r.y;
                }
                *(float2*)(C + (size_t)row1 * N + col) = make_float2(v2, v3);
            }
        }
    }
}

// ---------------------------------------------------------------------------
// adaLN modulation
// ---------------------------------------------------------------------------
__global__ void __launch_bounds__(256) mod_kernel(
    const float* __restrict__ c, const float* __restrict__ W,
    const float* __restrict__ bias)
{
    const int b = blockIdx.y;
    const int col = blockIdx.x * 256 + threadIdx.x;
    __shared__ float sc[DM];
    for (int i = threadIdx.x; i < DM; i += 256) {
        float v = c[b * DM + i];
        sc[i] = v / (1.0f + __expf(-v));
    }
    __syncthreads();
    float acc = 0.0f;
#pragma unroll 8
    for (int k = 0; k < DM; k++)
        acc = fmaf(sc[k], W[(size_t)k * (6 * DM) + col], acc);
    g_mod[b * 6 * DM + col] = acc + bias[col];
}

// ---------------------------------------------------------------------------
// LayerNorm + modulate (output rounded to tf32 — feeds GEMMs only)
// ---------------------------------------------------------------------------
__global__ void __launch_bounds__(256) lnmod_kernel(
    const float* __restrict__ x, int shOff, int scOff, float* __restrict__ out)
{
    const int row = blockIdx.x;
    const int b = row >> 10;
    const int tid = threadIdx.x;

    float4 v = ((const float4*)(x + (size_t)row * DM))[tid];
    float s  = v.x + v.y + v.z + v.w;
    float s2 = v.x * v.x + v.y * v.y + v.z * v.z + v.w * v.w;

    __shared__ float red[16];
#pragma unroll
    for (int off = 16; off > 0; off >>= 1) {
        s  += __shfl_xor_sync(0xffffffffu, s,  off);
        s2 += __shfl_xor_sync(0xffffffffu, s2, off);
    }
    const int warp = tid >> 5, lane = tid & 31;
    if (lane == 0) { red[warp] = s; red[warp + 8] = s2; }
    __syncthreads();
    if (tid == 0) {
        float ts = 0.f, ts2 = 0.f;
#pragma unroll
        for (int i = 0; i < 8; i++) { ts += red[i]; ts2 += red[i + 8]; }
        float mu  = ts * (1.0f / DM);
        float var = ts2 * (1.0f / DM) - mu * mu;
        red[0] = mu;
        red[1] = rsqrtf(var + 1e-6f);
    }
    __syncthreads();
    const float mu = red[0], rs = red[1];

    const float* modp = g_mod + b * 6 * DM;
    const int cc = tid * 4;
    float4 sh  = *(const float4*)(modp + shOff + cc);
    float4 scv = *(const float4*)(modp + scOff + cc);
    float4 o;
    o.x = rnaf((v.x - mu) * rs * (1.0f + scv.x) + sh.x);
    o.y = rnaf((v.y - mu) * rs * (1.0f + scv.y) + sh.y);
    o.z = rnaf((v.z - mu) * rs * (1.0f + scv.z) + sh.z);
    o.w = rnaf((v.w - mu) * rs * (1.0f + scv.w) + sh.w);
    ((float4*)(out + (size_t)row * DM))[tid] = o;
}

// ---------------------------------------------------------------------------
// Tensor-core flash self-attention v3.
// qkv is pre-rounded tf32 (ROUND qkv GEMM) -> staging is a raw copy, Q scale
// by 2^-3 is exact, so NO cvts anywhere in this kernel's mainloop.
// Output rounded to tf32 (feeds proj GEMM).
// ---------------------------------------------------------------------------
#define KS_PITCH 76
#define VS_PITCH 88

__global__ void __launch_bounds__(128) flash_attn_kernel()
{
    __shared__ uint32_t Ks[64][KS_PITCH];
    __shared__ uint32_t Vs[64][VS_PITCH];

    const int qt = blockIdx.x, h = blockIdx.y, b = blockIdx.z;
    const int tid  = threadIdx.x;
    const int lane = tid & 31;
    const int warp = tid >> 5;
    const int g = lane >> 2;
    const int t = lane & 3;
    const int rw = warp * 32;
    const int qbase = b * NSEQ + qt * 128;

    uint32_t qa[8][2][4];
#pragma unroll
    for (int mt = 0; mt < 2; mt++) {
        const float* q0 = g_qkv + (size_t)(qbase + rw + mt * 16 + g) * (3 * DM) + h * 64;
        const float* q1 = q0 + (size_t)8 * (3 * DM);
#pragma unroll
        for (int ks = 0; ks < 8; ks++) {
            qa[ks][mt][0] = __float_as_uint(q0[ks * 8 + t]     * 0.125f);
            qa[ks][mt][1] = __float_as_uint(q1[ks * 8 + t]     * 0.125f);
            qa[ks][mt][2] = __float_as_uint(q0[ks * 8 + t + 4] * 0.125f);
            qa[ks][mt][3] = __float_as_uint(q1[ks * 8 + t + 4] * 0.125f);
        }
    }

    float o[2][8][4];
#pragma unroll
    for (int mt = 0; mt < 2; mt++)
#pragma unroll
        for (int nt = 0; nt < 8; nt++)
#pragma unroll
            for (int i = 0; i < 4; i++) o[mt][nt][i] = 0.0f;
    float mrow[2][2] = {{-1e30f, -1e30f}, {-1e30f, -1e30f}};
    float lrow[2][2] = {{0.f, 0.f}, {0.f, 0.f}};

    const int j8  = lane & 7;
    const int mtx = lane >> 3;
    const uint32_t ksBase = (uint32_t)__cvta_generic_to_shared(&Ks[0][0]);
    uint32_t kAddr[2];
#pragma unroll
    for (int p = 0; p < 2; p++)
        kAddr[p] = ksBase +
            ((p * 16 + (mtx >> 1) * 8 + j8) * KS_PITCH + (mtx & 1) * 4) * 4;

    const int src0 = (lane & ~3) | (t >> 1);
    const int src2 = src0 + 2;
    const bool odd = (t & 1) != 0;

    for (int kt = 0; kt < 16; kt++) {
        __syncthreads();
#pragma unroll
        for (int i = 0; i < 8; i++) {
            const int f4 = tid + i * 128;
            const int rk = f4 >> 4, c4 = f4 & 15;
            const size_t krow = (size_t)(b * NSEQ + kt * 64 + rk) * (3 * DM);
            *(uint4*)&Ks[rk][c4 * 4] =
                *(const uint4*)(g_qkv + krow + DM     + h * 64 + c4 * 4);
            *(uint4*)&Vs[rk][c4 * 4] =
                *(const uint4*)(g_qkv + krow + 2 * DM + h * 64 + c4 * 4);
        }
        __syncthreads();

#pragma unroll
        for (int c = 0; c < 2; c++) {
            float s[2][4][4];
#pragma unroll
            for (int mt = 0; mt < 2; mt++)
#pragma unroll
                for (int nt = 0; nt < 4; nt++)
#pragma unroll
                    for (int i = 0; i < 4; i++) s[mt][nt][i] = 0.0f;

#pragma unroll
            for (int ks = 0; ks < 8; ks++) {
                uint32_t bq[2][4];
#pragma unroll
                for (int p = 0; p < 2; p++)
                    ldsm4(bq[p], kAddr[p] + c * (32 * KS_PITCH * 4) + ks * 32);
#pragma unroll
                for (int mt = 0; mt < 2; mt++) {
                    mma1688(s[mt][0], qa[ks][mt], &bq[0][0]);
                    mma1688(s[mt][1], qa[ks][mt], &bq[0][2]);
                    mma1688(s[mt][2], qa[ks][mt], &bq[1][0]);
                    mma1688(s[mt][3], qa[ks][mt], &bq[1][2]);
                }
            }

#pragma unroll
            for (int mt = 0; mt < 2; mt++) {
                float tmax0 = -1e30f, tmax1 = -1e30f;
#pragma unroll
                for (int nt = 0; nt < 4; nt++) {
                    tmax0 = fmaxf(tmax0, fmaxf(s[mt][nt][0], s[mt][nt][1]));
                    tmax1 = fmaxf(tmax1, fmaxf(s[mt][nt][2], s[mt][nt][3]));
                }
                tmax0 = fmaxf(tmax0, __shfl_xor_sync(0xffffffffu, tmax0, 1));
                tmax0 = fmaxf(tmax0, __shfl_xor_sync(0xffffffffu, tmax0, 2));
                tmax1 = fmaxf(tmax1, __shfl_xor_sync(0xffffffffu, tmax1, 1));
                tmax1 = fmaxf(tmax1, __shfl_xor_sync(0xffffffffu, tmax1, 2));

                const float mn0 = fmaxf(mrow[mt][0], tmax0);
                const float mn1 = fmaxf(mrow[mt][1], tmax1);
                const float corr0 = __expf(mrow[mt][0] - mn0);
                const float corr1 = __expf(mrow[mt][1] - mn1);

                float sum0 = 0.f, sum1 = 0.f;
#pragma unroll
                for (int nt = 0; nt < 4; nt++) {
                    s[mt][nt][0] = __expf(s[mt][nt][0] - mn0); sum0 += s[mt][nt][0];
                    s[mt][nt][1] = __expf(s[mt][nt][1] - mn0); sum0 += s[mt][nt][1];
                    s[mt][nt][2] = __expf(s[mt][nt][2] - mn1); sum1 += s[mt][nt][2];
                    s[mt][nt][3] = __expf(s[mt][nt][3] - mn1); sum1 += s[mt][nt][3];
                }
                sum0 += __shfl_xor_sync(0xffffffffu, sum0, 1);
                sum0 += __shfl_xor_sync(0xffffffffu, sum0, 2);
                sum1 += __shfl_xor_sync(0xffffffffu, sum1, 1);
                sum1 += __shfl_xor_sync(0xffffffffu, sum1, 2);

                lrow[mt][0] = lrow[mt][0] * corr0 + sum0;
                lrow[mt][1] = lrow[mt][1] * corr1 + sum1;
                mrow[mt][0] = mn0; mrow[mt][1] = mn1;
#pragma unroll
                for (int nt = 0; nt < 8; nt++) {
                    o[mt][nt][0] *= corr0; o[mt][nt][1] *= corr0;
                    o[mt][nt][2] *= corr1; o[mt][nt][3] *= corr1;
                }
            }

#pragma unroll
            for (int kv_ = 0; kv_ < 4; kv_++) {
                const int kk = c * 32 + kv_ * 8;
                uint32_t pa[2][4];
#pragma unroll
                for (int mt = 0; mt < 2; mt++) {
                    float v0 = __shfl_sync(0xffffffffu, s[mt][kv_][0], src0);
                    float v1 = __shfl_sync(0xffffffffu, s[mt][kv_][1], src0);
                    float v2 = __shfl_sync(0xffffffffu, s[mt][kv_][2], src0);
                    float v3 = __shfl_sync(0xffffffffu, s[mt][kv_][3], src0);
                    float w0 = __shfl_sync(0xffffffffu, s[mt][kv_][0], src2);
                    float w1 = __shfl_sync(0xffffffffu, s[mt][kv_][1], src2);
                    float w2 = __shfl_sync(0xffffffffu, s[mt][kv_][2], src2);
                    float w3 = __shfl_sync(0xffffffffu, s[mt][kv_][3], src2);
                    pa[mt][0] = __float_as_uint(odd ? v1 : v0);
                    pa[mt][1] = __float_as_uint(odd ? v3 : v2);
                    pa[mt][2] = __float_as_uint(odd ? w1 : w0);
                    pa[mt][3] = __float_as_uint(odd ? w3 : w2);
                }
#pragma unroll
                for (int nt = 0; nt < 8; nt++) {
                    uint32_t bv[2];
                    bv[0] = Vs[kk + t][nt * 8 + g];
                    bv[1] = Vs[kk + t + 4][nt * 8 + g];
                    mma1688(o[0][nt], pa[0], bv);
                    mma1688(o[1][nt], pa[1], bv);
                }
            }
        }
    }

#pragma unroll
    for (int mt = 0; mt < 2; mt++) {
        const float inv0 = 1.0f / lrow[mt][0];
        const float inv1 = 1.0f / lrow[mt][1];
        float* op0 = g_attn + (size_t)(qbase + rw + mt * 16 + g) * DM + h * 64;
        float* op1 = op0 + (size_t)8 * DM;
#pragma unroll
        for (int nt = 0; nt < 8; nt++) {
            *(float2*)(op0 + nt * 8 + 2 * t) =
                make_float2(rnaf(o[mt][nt][0] * inv0), rnaf(o[mt][nt][1] * inv0));
            *(float2*)(op1 + nt * 8 + 2 * t) =
                make_float2(rnaf(o[mt][nt][2] * inv1), rnaf(o[mt][nt][3] * inv1));
        }
    }
}

// ---------------------------------------------------------------------------
// Cross-attention: 77 keys. Two-pass softmax. Output rounded (feeds out GEMM).
// ---------------------------------------------------------------------------
__global__ void __launch_bounds__(64) cross_attn_kernel()
{
    __shared__ float Kc[TL][64];
    __shared__ float Vc[TL][64];

    const int qt = blockIdx.x, h = blockIdx.y, b = blockIdx.z;
    const int tid = threadIdx.x;

    for (int i = tid; i < TL * 16; i += 64) {
        const int l = i >> 4;
        const int c4 = (i & 15);
        const size_t src = (size_t)(b * TL + l) * DM + h * 64 + c4 * 4;
        ((float4*)Kc[l])[c4] = *(const float4*)(g_kc + src);
        ((float4*)Vc[l])[c4] = *(const float4*)(g_vc + src);
    }
    __syncthreads();

    const int row = b * NSEQ + qt * 64 + tid;
    float q[64];
    {
        const float4* qp = (const float4*)(g_qb + (size_t)row * DM + h * 64);
#pragma unroll
        for (int i = 0; i < 16; i++) {
            float4 tq = qp[i];
            q[4 * i + 0] = tq.x * 0.125f;
            q[4 * i + 1] = tq.y * 0.125f;
            q[4 * i + 2] = tq.z * 0.125f;
            q[4 * i + 3] = tq.w * 0.125f;
        }
    }

    float m = -1e30f;
    for (int l = 0; l < TL; l++) {
        const float4* kr = (const float4*)Kc[l];
        float s0 = 0.f, s1 = 0.f, s2 = 0.f, s3 = 0.f;
#pragma unroll
        for (int i = 0; i < 16; i++) {
            float4 kv = kr[i];
            s0 = fmaf(q[4 * i + 0], kv.x, s0);
            s1 = fmaf(q[4 * i + 1], kv.y, s1);
            s2 = fmaf(q[4 * i + 2], kv.z, s2);
            s3 = fmaf(q[4 * i + 3], kv.w, s3);
        }
        m = fmaxf(m, (s0 + s1) + (s2 + s3));
    }

    float o[64];
#pragma unroll
    for (int d = 0; d < 64; d++) o[d] = 0.0f;
    float lsum = 0.0f;
    for (int l = 0; l < TL; l++) {
        const float4* kr = (const float4*)Kc[l];
        float s0 = 0.f, s1 = 0.f, s2 = 0.f, s3 = 0.f;
#pragma unroll
        for (int i = 0; i < 16; i++) {
            float4 kv = kr[i];
            s0 = fmaf(q[4 * i + 0], kv.x, s0);
            s1 = fmaf(q[4 * i + 1], kv.y, s1);
            s2 = fmaf(q[4 * i + 2], kv.z, s2);
            s3 = fmaf(q[4 * i + 3], kv.w, s3);
        }
        const float p = __expf((s0 + s1) + (s2 + s3) - m);
        lsum += p;
        const float4* vr = (const float4*)Vc[l];
#pragma unroll
        for (int i = 0; i < 16; i++) {
            float4 vv = vr[i];
            o[4 * i + 0] = fmaf(p, vv.x, o[4 * i + 0]);
            o[4 * i + 1] = fmaf(p, vv.y, o[4 * i + 1]);
            o[4 * i + 2] = fmaf(p, vv.z, o[4 * i + 2]);
            o[4 * i + 3] = fmaf(p, vv.w, o[4 * i + 3]);
        }
    }

    const float inv = 1.0f / lsum;
    float4* op = (float4*)(g_attn + (size_t)row * DM + h * 64);
#pragma unroll
    for (int i = 0; i < 16; i++)
        op[i] = make_float4(rnaf(o[4 * i + 0] * inv), rnaf(o[4 * i + 1] * inv),
                            rnaf(o[4 * i + 2] * inv), rnaf(o[4 * i + 3] * inv));
}

// ---------------------------------------------------------------------------
// Host side
// ---------------------------------------------------------------------------
template <int EPI, bool ROUND = false>
static void launch_gemm(const float* A, const uint32_t* W, const float* bias,
                        const float* res, float* C, int M, int N, int K)
{
    dim3 grid(N / 128, (M + 127) / 128);
    tgemm_kernel<EPI, ROUND><<<grid, 128>>>(A, W, bias, res, C, M, N, K);
}

static void launch_cvt(const float* src, uint32_t* dst, int n)
{
    cvt_kernel<<<(n / 4 + 255) / 256, 256>>>(src, dst, n);
}

extern "C" void kernel_launch(void* const* d_in, const int* in_sizes, int n_in,
                              void* d_out, int out_size)
{
    const float* x       = (const float*)d_in[0];
    const float* c       = (const float*)d_in[1];
    const float* text    = (const float*)d_in[2];
    const float* W_ada   = (const float*)d_in[3];
    const float* b_ada   = (const float*)d_in[4];
    const float* W_qkv   = (const float*)d_in[5];
    const float* b_qkv   = (const float*)d_in[6];
    const float* W_proj  = (const float*)d_in[7];
    const float* b_proj  = (const float*)d_in[8];
    const float* W_ctx   = (const float*)d_in[9];
    const float* b_ctx   = (const float*)d_in[10];
    const float* W_q     = (const float*)d_in[11];
    const float* W_k     = (const float*)d_in[12];
    const float* W_v     = (const float*)d_in[13];
    const float* W_out   = (const float*)d_in[14];
    const float* b_out   = (const float*)d_in[15];
    const float* W_fc1   = (const float*)d_in[16];
    const float* b_fc1   = (const float*)d_in[17];
    const float* W_fc2   = (const float*)d_in[18];
    const float* b_fc2   = (const float*)d_in[19];
    float* out = (float*)d_out;

    float *p_h, *p_qkv, *p_attn, *p_x1, *p_x2, *p_ctx, *p_qb, *p_kc, *p_vc, *p_hidden;
    uint32_t* p_wc;
    cudaGetSymbolAddress((void**)&p_h,      g_h);
    cudaGetSymbolAddress((void**)&p_qkv,    g_qkv);
    cudaGetSymbolAddress((void**)&p_attn,   g_attn);
    cudaGetSymbolAddress((void**)&p_x1,     g_x1);
    cudaGetSymbolAddress((void**)&p_x2,     g_x2);
    cudaGetSymbolAddress((void**)&p_ctx,    g_ctx);
    cudaGetSymbolAddress((void**)&p_qb,     g_qb);
    cudaGetSymbolAddress((void**)&p_kc,     g_kc);
    cudaGetSymbolAddress((void**)&p_vc,     g_vc);
    cudaGetSymbolAddress((void**)&p_hidden, g_hidden);
    cudaGetSymbolAddress((void**)&p_wc,     g_wc);

    // 0. Pre-convert weights + text to tf32 (RNA) scratch
    launch_cvt(W_qkv,  p_wc + OFF_QKV,  1024 * 3072);
    launch_cvt(W_proj, p_wc + OFF_PROJ, 1024 * 1024);
    launch_cvt(W_ctx,  p_wc + OFF_CTX,  768 * 1024);
    launch_cvt(W_q,    p_wc + OFF_Q,    1024 * 1024);
    launch_cvt(W_k,    p_wc + OFF_K,    1024 * 1024);
    launch_cvt(W_v,    p_wc + OFF_V,    1024 * 1024);
    launch_cvt(W_out,  p_wc + OFF_OUT,  1024 * 1024);
    launch_cvt(W_fc1,  p_wc + OFF_FC1,  1024 * 4096);
    launch_cvt(W_fc2,  p_wc + OFF_FC2,  4096 * 1024);
    launch_cvt(text,   p_wc + OFF_TEXT, BB * TL * TD);

    // 1. adaLN modulation
    {
        dim3 grid(6 * DM / 256, BB);
        mod_kernel<<<grid, 256>>>(c, W_ada, b_ada);
    }

    // --- self-attention block ---
    lnmod_kernel<<<TTOK, 256>>>(x, 0 * DM, 1 * DM, p_h);
    launch_gemm<EPI_BIAS, true>(p_h, p_wc + OFF_QKV, b_qkv, nullptr, p_qkv, TTOK, 3 * DM, DM);
    {
        dim3 grid(NSEQ / 128, NH, BB);
        flash_attn_kernel<<<grid, 128>>>();
    }
    launch_gemm<EPI_BIAS_RES>(p_attn, p_wc + OFF_PROJ, b_proj, x, p_x1, TTOK, DM, DM);

    // --- cross-attention block ---
    lnmod_kernel<<<TTOK, 256>>>(p_x1, 2 * DM, 3 * DM, p_h);
    launch_gemm<EPI_BIAS, true>((const float*)(p_wc + OFF_TEXT), p_wc + OFF_CTX,
                                b_ctx, nullptr, p_ctx, TCTX, DM, TD);
    launch_gemm<EPI_NOBIAS>(p_h, p_wc + OFF_Q, nullptr, nullptr, p_qb, TTOK, DM, DM);
    launch_gemm<EPI_NOBIAS>(p_ctx, p_wc + OFF_K, nullptr, nullptr, p_kc, TCTX, DM, DM);
    launch_gemm<EPI_NOBIAS>(p_ctx, p_wc + OFF_V, nullptr, nullptr, p_vc, TCTX, DM, DM);
    {
        dim3 grid(NSEQ / 64, NH, BB);
        cross_attn_kernel<<<grid, 64>>>();
    }
    launch_gemm<EPI_BIAS_RES>(p_attn, p_wc + OFF_OUT, b_out, p_x1, p_x2, TTOK, DM, DM);

    // --- MLP block ---
    lnmod_kernel<<<TTOK, 256>>>(p_x2, 4 * DM, 5 * DM, p_h);
    launch_gemm<EPI_BIAS_GELU, true>(p_h, p_wc + OFF_FC1, b_fc1, nullptr, p_hidden, TTOK, 4 * DM, DM);
    launch_gemm<EPI_BIAS_RES>(p_hidden, p_wc + OFF_FC2, b_fc2, p_x2, out, TTOK, DM, 4 * DM);
}